// round 12
// baseline (speedup 1.0000x reference)
#include <cuda_runtime.h>
#include <cuda_bf16.h>
#include <cstdint>
#include <stdint.h>
#include <math.h>

#define NUSER 100000
#define NITEM 200000
#define NALL  300000
#define HID   128
#define EUI   2000000
#define EUU   800000
#define LUI   3
#define LUU   2

#define APITCH 136   // bf16 elements per SMEM row (272B)
// smem: A hi/lo (64 rows) + W hi/lo (128 rows), bf16
#define FUSE_SMEM ((2 * 64 + 2 * 128) * APITCH * 2)   // 104448 B -> 2 CTAs/SM

// ---------------------------------------------------------------------------
// Scratch (device globals — no allocation allowed)
// ---------------------------------------------------------------------------
__device__ float g_emb [(size_t)NALL * HID];   // ping
__device__ float g_emb2[(size_t)NALL * HID];   // pong

__device__ int   g_rp_ui [NALL + 1];
__device__ int   g_cur_ui[NALL];
__device__ int   g_col_ui[EUI];
__device__ int   g_rp_uu [NUSER + 1];
__device__ int   g_cur_uu[NUSER];
__device__ int   g_col_uu[EUU];

__device__ int   g_do_ui[NALL];
__device__ int   g_di_ui[NALL];
__device__ int   g_do_uu[NUSER];
__device__ int   g_di_uu[NUSER];

__device__ float g_os_ui[NALL];
__device__ float g_is_ui[NALL];
__device__ float g_os_uu[NUSER];
__device__ float g_is_uu[NUSER];

__device__ int   g_bsum[512];

// ---------------------------------------------------------------------------
// Preprocessing kernels (unchanged from passing R9 kernel)
// ---------------------------------------------------------------------------
__global__ void k_hist(const int* __restrict__ src, const int* __restrict__ dst,
                       int E, int* __restrict__ dsrc, int* __restrict__ ddst) {
    int i = blockIdx.x * blockDim.x + threadIdx.x;
    if (i < E) {
        atomicAdd(&dsrc[src[i]], 1);
        atomicAdd(&ddst[dst[i]], 1);
    }
}

__global__ void k_scan_block(const int* __restrict__ deg, int n,
                             int* __restrict__ out, int* __restrict__ bsum) {
    __shared__ int s[1024];
    int tid = threadIdx.x;
    int i = blockIdx.x * 1024 + tid;
    int v = (i < n) ? deg[i] : 0;
    s[tid] = v;
    __syncthreads();
    for (int off = 1; off < 1024; off <<= 1) {
        int t = (tid >= off) ? s[tid - off] : 0;
        __syncthreads();
        s[tid] += t;
        __syncthreads();
    }
    if (i <= n) out[i] = s[tid] - v;
    if (tid == 1023) bsum[blockIdx.x] = s[1023];
}

__global__ void k_scan_sums(int* __restrict__ bs, int nb) {
    __shared__ int s[512];
    int tid = threadIdx.x;
    int v = (tid < nb) ? bs[tid] : 0;
    s[tid] = v;
    __syncthreads();
    for (int off = 1; off < 512; off <<= 1) {
        int t = (tid >= off) ? s[tid - off] : 0;
        __syncthreads();
        s[tid] += t;
        __syncthreads();
    }
    if (tid < nb) bs[tid] = s[tid] - v;
}

__global__ void k_add(int* __restrict__ rp, int* __restrict__ cur,
                      const int* __restrict__ bs, int total) {
    int i = blockIdx.x * blockDim.x + threadIdx.x;
    if (i < total) {
        int v = rp[i] + bs[i >> 10];
        rp[i] = v;
        if (i < total - 1) cur[i] = v;
    }
}

__global__ void k_scales(const int* __restrict__ dout, const int* __restrict__ din,
                         float* __restrict__ os, float* __restrict__ is_, int n) {
    int i = blockIdx.x * blockDim.x + threadIdx.x;
    if (i < n) {
        os[i]  = rsqrtf(fmaxf((float)dout[i], 1.0f));
        is_[i] = rsqrtf(fmaxf((float)din[i],  1.0f));
    }
}

__global__ void k_scatter(const int* __restrict__ src, const int* __restrict__ dst,
                          int E, int* __restrict__ cur, int* __restrict__ col) {
    int i = blockIdx.x * blockDim.x + threadIdx.x;
    if (i < E) {
        int pos = atomicAdd(&cur[dst[i]], 1);
        col[pos] = src[i];
    }
}

__global__ void k_sortrows(const int* __restrict__ rp, int* __restrict__ col, int n) {
    int i = blockIdx.x * blockDim.x + threadIdx.x;
    if (i >= n) return;
    int b = rp[i], e = rp[i + 1];
    for (int j = b + 1; j < e; j++) {
        int key = col[j];
        int k = j - 1;
        while (k >= b && col[k] > key) { col[k + 1] = col[k]; k--; }
        col[k + 1] = key;
    }
}

// ---------------------------------------------------------------------------
// MMA helpers (unchanged, proven in R9)
// ---------------------------------------------------------------------------
__device__ __forceinline__ void cvt_split4(float4 v,
        __nv_bfloat162& h01, __nv_bfloat162& h23,
        __nv_bfloat162& l01, __nv_bfloat162& l23) {
    __nv_bfloat16 hx = __float2bfloat16_rn(v.x);
    __nv_bfloat16 hy = __float2bfloat16_rn(v.y);
    __nv_bfloat16 hz = __float2bfloat16_rn(v.z);
    __nv_bfloat16 hw = __float2bfloat16_rn(v.w);
    __nv_bfloat16 lx = __float2bfloat16_rn(v.x - __bfloat162float(hx));
    __nv_bfloat16 ly = __float2bfloat16_rn(v.y - __bfloat162float(hy));
    __nv_bfloat16 lz = __float2bfloat16_rn(v.z - __bfloat162float(hz));
    __nv_bfloat16 lw = __float2bfloat16_rn(v.w - __bfloat162float(hw));
    h01 = __nv_bfloat162(hx, hy); h23 = __nv_bfloat162(hz, hw);
    l01 = __nv_bfloat162(lx, ly); l23 = __nv_bfloat162(lz, lw);
}

__device__ __forceinline__ unsigned int smem_u32(const void* p) {
    return (unsigned int)__cvta_generic_to_shared(p);
}

__device__ __forceinline__ void ldsm_x4(unsigned int addr,
        unsigned int& r0, unsigned int& r1, unsigned int& r2, unsigned int& r3) {
    asm volatile("ldmatrix.sync.aligned.m8n8.x4.shared.b16 {%0,%1,%2,%3}, [%4];"
                 : "=r"(r0), "=r"(r1), "=r"(r2), "=r"(r3) : "r"(addr));
}
__device__ __forceinline__ void ldsm_x4t(unsigned int addr,
        unsigned int& r0, unsigned int& r1, unsigned int& r2, unsigned int& r3) {
    asm volatile("ldmatrix.sync.aligned.m8n8.x4.trans.shared.b16 {%0,%1,%2,%3}, [%4];"
                 : "=r"(r0), "=r"(r1), "=r"(r2), "=r"(r3) : "r"(addr));
}
__device__ __forceinline__ void mma16816(float* c,
        unsigned int a0, unsigned int a1, unsigned int a2, unsigned int a3,
        unsigned int b0, unsigned int b1) {
    asm volatile("mma.sync.aligned.m16n8k16.row.col.f32.bf16.bf16.f32 "
                 "{%0,%1,%2,%3}, {%4,%5,%6,%7}, {%8,%9}, {%0,%1,%2,%3};"
                 : "+f"(c[0]), "+f"(c[1]), "+f"(c[2]), "+f"(c[3])
                 : "r"(a0), "r"(a1), "r"(a2), "r"(a3), "r"(b0), "r"(b1));
}

// ---------------------------------------------------------------------------
// Fused layer kernel: per 64-dst-row tile
//   phase U (mat=0): agg = Σ_{s<split} src[s]*os[s]  -> acc += agg @ Wu
//   phase V (mat=1): agg = Σ_{s>=NUSER} ...          -> acc += agg @ Wv
//   epilogue: rst = leaky(acc*is[d], 0.5); emb_out[d]=rst;
//             out[d] = (first? init[d] : out[d]) + rst/max(||rst||,1e-12)
// 256 threads: 8 warps gather 8 rows each; warps 0-3 run MMA (16 rows each).
// ---------------------------------------------------------------------------
__global__ __launch_bounds__(256, 2)
void k_fused(const float* __restrict__ srcA, const float* __restrict__ srcB,
             const float* __restrict__ Wu, const float* __restrict__ Wv,
             const int* __restrict__ rp, const int* __restrict__ col,
             const float* __restrict__ osc, const float* __restrict__ isc,
             float* __restrict__ emb_out, float* __restrict__ acc_out,
             int n, int nmats,
             int first, const float* __restrict__ initA,
             const float* __restrict__ initB, int thresh) {
    extern __shared__ __align__(16) unsigned char smem[];
    __nv_bfloat16* Ah = reinterpret_cast<__nv_bfloat16*>(smem);
    __nv_bfloat16* Al = Ah + 64 * APITCH;
    __nv_bfloat16* Wh = Al + 64 * APITCH;
    __nv_bfloat16* Wl = Wh + 128 * APITCH;

    const int tid  = threadIdx.x;
    const int lane = tid & 31;
    const int w    = tid >> 5;           // 0..7
    const int row0 = blockIdx.x * 64;
    const int split = (nmats == 2) ? NUSER : 0x7fffffff;

    float acc[16][4];
#pragma unroll
    for (int i = 0; i < 16; i++)
#pragma unroll
        for (int j = 0; j < 4; j++) acc[i][j] = 0.0f;

    for (int mat = 0; mat < nmats; mat++) {
        if (mat) __syncthreads();        // prior MMA done before smem overwrite

        // ---- stage W[mat] (hi/lo split), 256 thr x 16 iters = 4096 float4 ----
        const float* W = (mat == 0) ? Wu : Wv;
#pragma unroll
        for (int i = 0; i < 16; i++) {
            int idx = tid + i * 256;
            int r  = idx >> 5;           // k-row 0..127
            int c4 = idx & 31;
            float4 vw = *reinterpret_cast<const float4*>(W + (size_t)r * 128 + c4 * 4);
            __nv_bfloat162 h01, h23, l01, l23;
            cvt_split4(vw, h01, h23, l01, l23);
            __nv_bfloat162* pw = reinterpret_cast<__nv_bfloat162*>(Wh + r * APITCH + c4 * 4);
            pw[0] = h01; pw[1] = h23;
            __nv_bfloat162* pwl = reinterpret_cast<__nv_bfloat162*>(Wl + r * APITCH + c4 * 4);
            pwl[0] = l01; pwl[1] = l23;
        }

        // ---- gather+aggregate: warp w owns local rows w*8 .. w*8+7 ----
        for (int rr = 0; rr < 8; rr++) {
            int lr = w * 8 + rr;
            int gr = row0 + lr;
            float4 a = make_float4(0.f, 0.f, 0.f, 0.f);
            if (gr < n) {
                int b = rp[gr], e = rp[gr + 1];
                for (int j = b; j < e; j += 4) {
#pragma unroll
                    for (int q = 0; q < 4; q++) {
                        int jj = j + q;
                        bool valid = jj < e;
                        int s = valid ? __ldg(col + jj) : 0;
                        bool take = valid &&
                            ((mat == 0) ? (s < split) : (s >= NUSER));
                        const float* base = (mat == 0)
                            ? (srcA + (size_t)s * HID)
                            : (srcB + (size_t)(s - NUSER) * HID);
                        float4 v = take
                            ? __ldg(reinterpret_cast<const float4*>(base) + lane)
                            : make_float4(0.f, 0.f, 0.f, 0.f);
                        float o = take ? __ldg(osc + s) : 0.f;
                        a.x = fmaf(v.x, o, a.x);
                        a.y = fmaf(v.y, o, a.y);
                        a.z = fmaf(v.z, o, a.z);
                        a.w = fmaf(v.w, o, a.w);
                    }
                }
            }
            // store row lr as split bf16 (lane covers cols 4*lane..4*lane+3)
            __nv_bfloat162 h01, h23, l01, l23;
            cvt_split4(a, h01, h23, l01, l23);
            __nv_bfloat162* pa = reinterpret_cast<__nv_bfloat162*>(Ah + lr * APITCH + lane * 4);
            pa[0] = h01; pa[1] = h23;
            __nv_bfloat162* pal = reinterpret_cast<__nv_bfloat162*>(Al + lr * APITCH + lane * 4);
            pal[0] = l01; pal[1] = l23;
        }
        __syncthreads();

        // ---- MMA: warps 0..3, rows m0..m0+15, full N=128 ----
        if (w < 4) {
            const int m0 = w * 16;
            const int a_row  = m0 + (lane & 7) + (lane & 8);
            const int a_ksel = (lane >> 4) & 1;
            unsigned int aaddr_h = smem_u32(Ah + a_row * APITCH + a_ksel * 8);
            unsigned int aaddr_l = smem_u32(Al + a_row * APITCH + a_ksel * 8);
            const int b_krow = ((lane >> 4) & 1) * 8 + (lane & 7);
            const int b_nsel = (lane >> 3) & 1;
            unsigned int baddr_h = smem_u32(Wh + b_krow * APITCH + b_nsel * 8);
            unsigned int baddr_l = smem_u32(Wl + b_krow * APITCH + b_nsel * 8);

#pragma unroll
            for (int ks = 0; ks < 8; ks++) {
                const unsigned int koffA = ks * 32;
                const unsigned int koffB = ks * 16 * (APITCH * 2);
                unsigned int ah0, ah1, ah2, ah3, al0, al1, al2, al3;
                ldsm_x4(aaddr_h + koffA, ah0, ah1, ah2, ah3);
                ldsm_x4(aaddr_l + koffA, al0, al1, al2, al3);
#pragma unroll
                for (int ntp = 0; ntp < 8; ntp++) {
                    unsigned int noff = ntp * 32;
                    unsigned int bh0, bh1, bh2, bh3, bl0, bl1, bl2, bl3;
                    ldsm_x4t(baddr_h + koffB + noff, bh0, bh1, bh2, bh3);
                    ldsm_x4t(baddr_l + koffB + noff, bl0, bl1, bl2, bl3);
                    mma16816(acc[ntp * 2],     ah0, ah1, ah2, ah3, bh0, bh2);
                    mma16816(acc[ntp * 2],     al0, al1, al2, al3, bh0, bh2);
                    mma16816(acc[ntp * 2],     ah0, ah1, ah2, ah3, bl0, bl2);
                    mma16816(acc[ntp * 2 + 1], ah0, ah1, ah2, ah3, bh1, bh3);
                    mma16816(acc[ntp * 2 + 1], al0, al1, al2, al3, bh1, bh3);
                    mma16816(acc[ntp * 2 + 1], ah0, ah1, ah2, ah3, bl1, bl3);
                }
            }
        }
    }

    // ---- epilogue: warps 0..3 hold the 64-row result in fragments ----
    if (w < 4) {
        const int tr = lane >> 2;
        const int tc = (lane & 3) * 2;
        const int r_lo = row0 + w * 16 + tr;
        const int r_hi = r_lo + 8;
        float is_lo = (r_lo < n) ? __ldg(isc + r_lo) : 0.f;
        float is_hi = (r_hi < n) ? __ldg(isc + r_hi) : 0.f;

        float sq0 = 0.f, sq1 = 0.f;
#pragma unroll
        for (int nt = 0; nt < 16; nt++) {
            float v0 = acc[nt][0] * is_lo;
            float v1 = acc[nt][1] * is_lo;
            float v2 = acc[nt][2] * is_hi;
            float v3 = acc[nt][3] * is_hi;
            v0 = v0 >= 0.f ? v0 : 0.5f * v0;
            v1 = v1 >= 0.f ? v1 : 0.5f * v1;
            v2 = v2 >= 0.f ? v2 : 0.5f * v2;
            v3 = v3 >= 0.f ? v3 : 0.5f * v3;
            acc[nt][0] = v0; acc[nt][1] = v1; acc[nt][2] = v2; acc[nt][3] = v3;
            sq0 = fmaf(v0, v0, fmaf(v1, v1, sq0));
            sq1 = fmaf(v2, v2, fmaf(v3, v3, sq1));
        }
        // reduce over the 4 lanes of each row group (lane^1, lane^2)
        sq0 += __shfl_xor_sync(0xffffffffu, sq0, 1);
        sq0 += __shfl_xor_sync(0xffffffffu, sq0, 2);
        sq1 += __shfl_xor_sync(0xffffffffu, sq1, 1);
        sq1 += __shfl_xor_sync(0xffffffffu, sq1, 2);
        float inv0 = 1.0f / fmaxf(sqrtf(sq0), 1e-12f);
        float inv1 = 1.0f / fmaxf(sqrtf(sq1), 1e-12f);

#pragma unroll
        for (int nt = 0; nt < 16; nt++) {
            int c = nt * 8 + tc;
            if (r_lo < n) {
                *reinterpret_cast<float2*>(emb_out + (size_t)r_lo * HID + c) =
                    make_float2(acc[nt][0], acc[nt][1]);
                float2 o;
                if (first) {
                    const float* ip = (r_lo < thresh)
                        ? (initA + (size_t)r_lo * HID)
                        : (initB + (size_t)(r_lo - thresh) * HID);
                    o = __ldg(reinterpret_cast<const float2*>(ip + c));
                } else {
                    o = *reinterpret_cast<const float2*>(acc_out + (size_t)r_lo * HID + c);
                }
                o.x += acc[nt][0] * inv0;
                o.y += acc[nt][1] * inv0;
                *reinterpret_cast<float2*>(acc_out + (size_t)r_lo * HID + c) = o;
            }
            if (r_hi < n) {
                *reinterpret_cast<float2*>(emb_out + (size_t)r_hi * HID + c) =
                    make_float2(acc[nt][2], acc[nt][3]);
                float2 o;
                if (first) {
                    const float* ip = (r_hi < thresh)
                        ? (initA + (size_t)r_hi * HID)
                        : (initB + (size_t)(r_hi - thresh) * HID);
                    o = __ldg(reinterpret_cast<const float2*>(ip + c));
                } else {
                    o = *reinterpret_cast<const float2*>(acc_out + (size_t)r_hi * HID + c);
                }
                o.x += acc[nt][2] * inv1;
                o.y += acc[nt][3] * inv1;
                *reinterpret_cast<float2*>(acc_out + (size_t)r_hi * HID + c) = o;
            }
        }
    }
}

// ---------------------------------------------------------------------------
// Launch
// ---------------------------------------------------------------------------
extern "C" void kernel_launch(void* const* d_in, const int* in_sizes, int n_in,
                              void* d_out, int out_size) {
    (void)in_sizes; (void)n_in; (void)out_size;
    const float* user_emb = (const float*)d_in[0];
    const float* item_emb = (const float*)d_in[1];
    const float* ui_u_w   = (const float*)d_in[2];
    const float* ui_v_w   = (const float*)d_in[3];
    const float* uu_u_w   = (const float*)d_in[4];
    const int*   src_ui   = (const int*)d_in[5];
    const int*   dst_ui   = (const int*)d_in[6];
    const int*   src_uu   = (const int*)d_in[7];
    const int*   dst_uu   = (const int*)d_in[8];
    float* out = (float*)d_out;

    void* p;
    float *embA, *embB, *os_ui, *is_ui, *os_uu, *is_uu;
    int *rp_ui, *cur_ui, *col_ui, *rp_uu, *cur_uu, *col_uu;
    int *do_ui, *di_ui, *do_uu, *di_uu, *bsum;
    cudaGetSymbolAddress(&p, g_emb);    embA   = (float*)p;
    cudaGetSymbolAddress(&p, g_emb2);   embB   = (float*)p;
    cudaGetSymbolAddress(&p, g_os_ui);  os_ui  = (float*)p;
    cudaGetSymbolAddress(&p, g_is_ui);  is_ui  = (float*)p;
    cudaGetSymbolAddress(&p, g_os_uu);  os_uu  = (float*)p;
    cudaGetSymbolAddress(&p, g_is_uu);  is_uu  = (float*)p;
    cudaGetSymbolAddress(&p, g_rp_ui);  rp_ui  = (int*)p;
    cudaGetSymbolAddress(&p, g_cur_ui); cur_ui = (int*)p;
    cudaGetSymbolAddress(&p, g_col_ui); col_ui = (int*)p;
    cudaGetSymbolAddress(&p, g_rp_uu);  rp_uu  = (int*)p;
    cudaGetSymbolAddress(&p, g_cur_uu); cur_uu = (int*)p;
    cudaGetSymbolAddress(&p, g_col_uu); col_uu = (int*)p;
    cudaGetSymbolAddress(&p, g_do_ui);  do_ui  = (int*)p;
    cudaGetSymbolAddress(&p, g_di_ui);  di_ui  = (int*)p;
    cudaGetSymbolAddress(&p, g_do_uu);  do_uu  = (int*)p;
    cudaGetSymbolAddress(&p, g_di_uu);  di_uu  = (int*)p;
    cudaGetSymbolAddress(&p, g_bsum);   bsum   = (int*)p;

    cudaFuncSetAttribute(k_fused, cudaFuncAttributeMaxDynamicSharedMemorySize, FUSE_SMEM);

    cudaStream_t st = 0;
    const int GA = (NALL  + 63) / 64;   // 4688
    const int GUU = (NUSER + 63) / 64;  // 1563
    const size_t WSTEP = (size_t)HID * HID;

    // ---- graph preprocessing ----
    cudaMemsetAsync(do_ui, 0, NALL  * sizeof(int), st);
    cudaMemsetAsync(di_ui, 0, NALL  * sizeof(int), st);
    cudaMemsetAsync(do_uu, 0, NUSER * sizeof(int), st);
    cudaMemsetAsync(di_uu, 0, NUSER * sizeof(int), st);
    k_hist<<<(EUI + 255) / 256, 256, 0, st>>>(src_ui, dst_ui, EUI, do_ui, di_ui);
    k_hist<<<(EUU + 255) / 256, 256, 0, st>>>(src_uu, dst_uu, EUU, do_uu, di_uu);
    {
        int nb = (NALL + 1 + 1023) / 1024;
        k_scan_block<<<nb, 1024, 0, st>>>(di_ui, NALL, rp_ui, bsum);
        k_scan_sums<<<1, 512, 0, st>>>(bsum, nb);
        k_add<<<(NALL + 1 + 255) / 256, 256, 0, st>>>(rp_ui, cur_ui, bsum, NALL + 1);
    }
    {
        int nb = (NUSER + 1 + 1023) / 1024;
        k_scan_block<<<nb, 1024, 0, st>>>(di_uu, NUSER, rp_uu, bsum);
        k_scan_sums<<<1, 512, 0, st>>>(bsum, nb);
        k_add<<<(NUSER + 1 + 255) / 256, 256, 0, st>>>(rp_uu, cur_uu, bsum, NUSER + 1);
    }
    k_scales<<<(NALL  + 255) / 256, 256, 0, st>>>(do_ui, di_ui, os_ui, is_ui, NALL);
    k_scales<<<(NUSER + 255) / 256, 256, 0, st>>>(do_uu, di_uu, os_uu, is_uu, NUSER);
    k_scatter<<<(EUI + 255) / 256, 256, 0, st>>>(src_ui, dst_ui, EUI, cur_ui, col_ui);
    k_scatter<<<(EUU + 255) / 256, 256, 0, st>>>(src_uu, dst_uu, EUU, cur_uu, col_uu);
    k_sortrows<<<(NALL  + 255) / 256, 256, 0, st>>>(rp_ui, col_ui, NALL);
    k_sortrows<<<(NUSER + 255) / 256, 256, 0, st>>>(rp_uu, col_uu, NUSER);

    // ---- user-item propagation: 3 fused layers, emb ping-pong ----
    // L0: sources = inputs, writes embA, initializes out
    k_fused<<<GA, 256, FUSE_SMEM, st>>>(
        user_emb, item_emb, ui_u_w, ui_v_w,
        rp_ui, col_ui, os_ui, is_ui,
        embA, out, NALL, 2,
        1, user_emb, item_emb, NUSER);
    // L1: embA -> embB
    k_fused<<<GA, 256, FUSE_SMEM, st>>>(
        embA, embA + (size_t)NUSER * HID, ui_u_w + WSTEP, ui_v_w + WSTEP,
        rp_ui, col_ui, os_ui, is_ui,
        embB, out, NALL, 2,
        0, user_emb, item_emb, NUSER);
    // L2: embB -> embA
    k_fused<<<GA, 256, FUSE_SMEM, st>>>(
        embB, embB + (size_t)NUSER * HID, ui_u_w + 2 * WSTEP, ui_v_w + 2 * WSTEP,
        rp_ui, col_ui, os_ui, is_ui,
        embA, out, NALL, 2,
        0, user_emb, item_emb, NUSER);

    // ---- user-user propagation: 2 fused layers (single weight) ----
    float* out_uu = out + (size_t)NALL * HID;
    // L0: user_emb -> embB, init out_uu
    k_fused<<<GUU, 256, FUSE_SMEM, st>>>(
        user_emb, user_emb, uu_u_w, uu_u_w,
        rp_uu, col_uu, os_uu, is_uu,
        embB, out_uu, NUSER, 1,
        1, user_emb, user_emb, NUSER);
    // L1: embB -> embA
    k_fused<<<GUU, 256, FUSE_SMEM, st>>>(
        embB, embB, uu_u_w + WSTEP, uu_u_w + WSTEP,
        rp_uu, col_uu, os_uu, is_uu,
        embA, out_uu, NUSER, 1,
        0, user_emb, user_emb, NUSER);
}

// round 13
// speedup vs baseline: 2.0833x; 2.0833x over previous
#include <cuda_runtime.h>
#include <cuda_bf16.h>
#include <cstdint>
#include <stdint.h>
#include <math.h>

// ---------------------------------------------------------------------------
// Problem constants
// ---------------------------------------------------------------------------
#define NUSER 100000
#define NITEM 200000
#define NALL  300000
#define HID   128
#define EUI   2000000
#define EUU   800000
#define LUI   3
#define LUU   2

#define APITCH 136   // bf16 elements per SMEM row (272B: conflict-free ldmatrix)
// smem: A hi/lo (64 rows) + W hi/lo (128 rows), bf16
#define GEMM_SMEM ((2 * 64 + 2 * 128) * APITCH * 2)   // 104448 B -> 2 CTAs/SM

// ---------------------------------------------------------------------------
// Scratch (device globals — no allocation allowed)
// ---------------------------------------------------------------------------
__device__ float g_emb  [(size_t)NALL * HID];
__device__ float g_nodef[(size_t)NALL * HID];

__device__ int   g_rp_ui [NALL + 1];
__device__ int   g_cur_ui[NALL];
__device__ int   g_col_ui[EUI];
__device__ int   g_rp_uu [NUSER + 1];
__device__ int   g_cur_uu[NUSER];
__device__ int   g_col_uu[EUU];

__device__ int   g_do_ui[NALL];
__device__ int   g_di_ui[NALL];
__device__ int   g_do_uu[NUSER];
__device__ int   g_di_uu[NUSER];

__device__ float g_os_ui[NALL];
__device__ float g_is_ui[NALL];
__device__ float g_os_uu[NUSER];
__device__ float g_is_uu[NUSER];

__device__ int   g_bsum[512];

// ---------------------------------------------------------------------------
// Preprocessing kernels
// ---------------------------------------------------------------------------
__global__ void k_hist(const int* __restrict__ src, const int* __restrict__ dst,
                       int E, int* __restrict__ dsrc, int* __restrict__ ddst) {
    int i = blockIdx.x * blockDim.x + threadIdx.x;
    if (i < E) {
        atomicAdd(&dsrc[src[i]], 1);
        atomicAdd(&ddst[dst[i]], 1);
    }
}

__global__ void k_scan_block(const int* __restrict__ deg, int n,
                             int* __restrict__ out, int* __restrict__ bsum) {
    __shared__ int s[1024];
    int tid = threadIdx.x;
    int i = blockIdx.x * 1024 + tid;
    int v = (i < n) ? deg[i] : 0;
    s[tid] = v;
    __syncthreads();
    for (int off = 1; off < 1024; off <<= 1) {
        int t = (tid >= off) ? s[tid - off] : 0;
        __syncthreads();
        s[tid] += t;
        __syncthreads();
    }
    if (i <= n) out[i] = s[tid] - v;
    if (tid == 1023) bsum[blockIdx.x] = s[1023];
}

__global__ void k_scan_sums(int* __restrict__ bs, int nb) {
    __shared__ int s[512];
    int tid = threadIdx.x;
    int v = (tid < nb) ? bs[tid] : 0;
    s[tid] = v;
    __syncthreads();
    for (int off = 1; off < 512; off <<= 1) {
        int t = (tid >= off) ? s[tid - off] : 0;
        __syncthreads();
        s[tid] += t;
        __syncthreads();
    }
    if (tid < nb) bs[tid] = s[tid] - v;
}

__global__ void k_add(int* __restrict__ rp, int* __restrict__ cur,
                      const int* __restrict__ bs, int total) {
    int i = blockIdx.x * blockDim.x + threadIdx.x;
    if (i < total) {
        int v = rp[i] + bs[i >> 10];
        rp[i] = v;
        if (i < total - 1) cur[i] = v;
    }
}

__global__ void k_scales(const int* __restrict__ dout, const int* __restrict__ din,
                         float* __restrict__ os, float* __restrict__ is_, int n) {
    int i = blockIdx.x * blockDim.x + threadIdx.x;
    if (i < n) {
        os[i]  = rsqrtf(fmaxf((float)dout[i], 1.0f));
        is_[i] = rsqrtf(fmaxf((float)din[i],  1.0f));
    }
}

__global__ void k_scatter(const int* __restrict__ src, const int* __restrict__ dst,
                          int E, int* __restrict__ cur, int* __restrict__ col) {
    int i = blockIdx.x * blockDim.x + threadIdx.x;
    if (i < E) {
        int pos = atomicAdd(&cur[dst[i]], 1);
        col[pos] = src[i];
    }
}

__global__ void k_sortrows(const int* __restrict__ rp, int* __restrict__ col, int n) {
    int i = blockIdx.x * blockDim.x + threadIdx.x;
    if (i >= n) return;
    int b = rp[i], e = rp[i + 1];
    for (int j = b + 1; j < e; j++) {
        int key = col[j];
        int k = j - 1;
        while (k >= b && col[k] > key) { col[k + 1] = col[k]; k--; }
        col[k + 1] = key;
    }
}

// ---------------------------------------------------------------------------
// Tensor-core GEMM: C = A @ W  (A:[M,128] fp32, W:[128,128] fp32 row-major)
// bf16 2-term split (Ah*Wh + Al*Wh + Ah*Wl) via mma.sync.m16n8k16.
// One block = 64 rows x 128 cols (4 warps), K=128 in one SMEM slab, 2 CTA/SM.
// ---------------------------------------------------------------------------
__device__ __forceinline__ void cvt_split4(float4 v,
        __nv_bfloat162& h01, __nv_bfloat162& h23,
        __nv_bfloat162& l01, __nv_bfloat162& l23) {
    __nv_bfloat16 hx = __float2bfloat16_rn(v.x);
    __nv_bfloat16 hy = __float2bfloat16_rn(v.y);
    __nv_bfloat16 hz = __float2bfloat16_rn(v.z);
    __nv_bfloat16 hw = __float2bfloat16_rn(v.w);
    __nv_bfloat16 lx = __float2bfloat16_rn(v.x - __bfloat162float(hx));
    __nv_bfloat16 ly = __float2bfloat16_rn(v.y - __bfloat162float(hy));
    __nv_bfloat16 lz = __float2bfloat16_rn(v.z - __bfloat162float(hz));
    __nv_bfloat16 lw = __float2bfloat16_rn(v.w - __bfloat162float(hw));
    h01 = __nv_bfloat162(hx, hy); h23 = __nv_bfloat162(hz, hw);
    l01 = __nv_bfloat162(lx, ly); l23 = __nv_bfloat162(lz, lw);
}

__device__ __forceinline__ unsigned int smem_u32(const void* p) {
    return (unsigned int)__cvta_generic_to_shared(p);
}

__device__ __forceinline__ void ldsm_x4(unsigned int addr,
        unsigned int& r0, unsigned int& r1, unsigned int& r2, unsigned int& r3) {
    asm volatile("ldmatrix.sync.aligned.m8n8.x4.shared.b16 {%0,%1,%2,%3}, [%4];"
                 : "=r"(r0), "=r"(r1), "=r"(r2), "=r"(r3) : "r"(addr));
}
__device__ __forceinline__ void ldsm_x4t(unsigned int addr,
        unsigned int& r0, unsigned int& r1, unsigned int& r2, unsigned int& r3) {
    asm volatile("ldmatrix.sync.aligned.m8n8.x4.trans.shared.b16 {%0,%1,%2,%3}, [%4];"
                 : "=r"(r0), "=r"(r1), "=r"(r2), "=r"(r3) : "r"(addr));
}
__device__ __forceinline__ void mma16816(float* c,
        unsigned int a0, unsigned int a1, unsigned int a2, unsigned int a3,
        unsigned int b0, unsigned int b1) {
    asm volatile("mma.sync.aligned.m16n8k16.row.col.f32.bf16.bf16.f32 "
                 "{%0,%1,%2,%3}, {%4,%5,%6,%7}, {%8,%9}, {%0,%1,%2,%3};"
                 : "+f"(c[0]), "+f"(c[1]), "+f"(c[2]), "+f"(c[3])
                 : "r"(a0), "r"(a1), "r"(a2), "r"(a3), "r"(b0), "r"(b1));
}

__global__ __launch_bounds__(128, 2)
void k_gemm(const float* __restrict__ A, const float* __restrict__ W,
            float* __restrict__ C, int M) {
    extern __shared__ __align__(16) unsigned char smem[];
    __nv_bfloat16* Ah = reinterpret_cast<__nv_bfloat16*>(smem);
    __nv_bfloat16* Al = Ah + 64 * APITCH;
    __nv_bfloat16* Wh = Al + 64 * APITCH;
    __nv_bfloat16* Wl = Wh + 128 * APITCH;

    const int tid = threadIdx.x;
    const int row0 = blockIdx.x * 64;

    // ---- stage A (64 rows) as bf16 hi/lo ----
#pragma unroll
    for (int i = 0; i < 16; i++) {
        int idx = tid + i * 128;           // 2048 float4
        int r  = idx >> 5;                 // 0..63
        int c4 = idx & 31;
        float4 va = make_float4(0.f, 0.f, 0.f, 0.f);
        if (row0 + r < M)
            va = *reinterpret_cast<const float4*>(A + (size_t)(row0 + r) * 128 + c4 * 4);
        __nv_bfloat162 h01, h23, l01, l23;
        cvt_split4(va, h01, h23, l01, l23);
        __nv_bfloat162* pa = reinterpret_cast<__nv_bfloat162*>(Ah + r * APITCH + c4 * 4);
        pa[0] = h01; pa[1] = h23;
        __nv_bfloat162* pal = reinterpret_cast<__nv_bfloat162*>(Al + r * APITCH + c4 * 4);
        pal[0] = l01; pal[1] = l23;
    }
    // ---- stage W (128 k-rows) as bf16 hi/lo ----
#pragma unroll
    for (int i = 0; i < 32; i++) {
        int idx = tid + i * 128;           // 4096 float4
        int r  = idx >> 5;                 // k row 0..127
        int c4 = idx & 31;
        float4 vw = *reinterpret_cast<const float4*>(W + (size_t)r * 128 + c4 * 4);
        __nv_bfloat162 h01, h23, l01, l23;
        cvt_split4(vw, h01, h23, l01, l23);
        __nv_bfloat162* pw = reinterpret_cast<__nv_bfloat162*>(Wh + r * APITCH + c4 * 4);
        pw[0] = h01; pw[1] = h23;
        __nv_bfloat162* pwl = reinterpret_cast<__nv_bfloat162*>(Wl + r * APITCH + c4 * 4);
        pwl[0] = l01; pwl[1] = l23;
    }
    __syncthreads();

    // ---- compute: warp w owns rows m0..m0+15, full N=128 ----
    const int lane = tid & 31;
    const int w    = tid >> 5;             // 0..3
    const int m0   = w * 16;

    float acc[16][4];
#pragma unroll
    for (int i = 0; i < 16; i++)
#pragma unroll
        for (int j = 0; j < 4; j++) acc[i][j] = 0.0f;

    const int a_row  = m0 + (lane & 7) + (lane & 8);
    const int a_ksel = (lane >> 4) & 1;
    unsigned int aaddr_h = smem_u32(Ah + a_row * APITCH + a_ksel * 8);
    unsigned int aaddr_l = smem_u32(Al + a_row * APITCH + a_ksel * 8);
    const int b_krow = ((lane >> 4) & 1) * 8 + (lane & 7);
    const int b_nsel = (lane >> 3) & 1;
    unsigned int baddr_h = smem_u32(Wh + b_krow * APITCH + b_nsel * 8);
    unsigned int baddr_l = smem_u32(Wl + b_krow * APITCH + b_nsel * 8);

#pragma unroll
    for (int ks = 0; ks < 8; ks++) {
        const unsigned int koffA = ks * 32;
        const unsigned int koffB = ks * 16 * (APITCH * 2);
        unsigned int ah0, ah1, ah2, ah3, al0, al1, al2, al3;
        ldsm_x4(aaddr_h + koffA, ah0, ah1, ah2, ah3);
        ldsm_x4(aaddr_l + koffA, al0, al1, al2, al3);
#pragma unroll
        for (int ntp = 0; ntp < 8; ntp++) {
            unsigned int noff = ntp * 32;
            unsigned int bh0, bh1, bh2, bh3, bl0, bl1, bl2, bl3;
            ldsm_x4t(baddr_h + koffB + noff, bh0, bh1, bh2, bh3);
            ldsm_x4t(baddr_l + koffB + noff, bl0, bl1, bl2, bl3);
            mma16816(acc[ntp * 2],     ah0, ah1, ah2, ah3, bh0, bh2);
            mma16816(acc[ntp * 2],     al0, al1, al2, al3, bh0, bh2);
            mma16816(acc[ntp * 2],     ah0, ah1, ah2, ah3, bl0, bl2);
            mma16816(acc[ntp * 2 + 1], ah0, ah1, ah2, ah3, bh1, bh3);
            mma16816(acc[ntp * 2 + 1], al0, al1, al2, al3, bh1, bh3);
            mma16816(acc[ntp * 2 + 1], ah0, ah1, ah2, ah3, bl1, bl3);
        }
    }

    // ---- epilogue ----
    const int tr = lane >> 2;
    const int tc = (lane & 3) * 2;
    const int r_lo = row0 + m0 + tr;
    const int r_hi = r_lo + 8;
#pragma unroll
    for (int nt = 0; nt < 16; nt++) {
        int col = nt * 8 + tc;
        if (r_lo < M)
            *reinterpret_cast<float2*>(C + (size_t)r_lo * 128 + col) =
                make_float2(acc[nt][0], acc[nt][1]);
        if (r_hi < M)
            *reinterpret_cast<float2*>(C + (size_t)r_hi * 128 + col) =
                make_float2(acc[nt][2], acc[nt][3]);
    }
}

// ---------------------------------------------------------------------------
// CSR SpMM + fused epilogue. One warp per destination row.
// 8-deep predicated unroll for MLP; summation order (sequential j) preserved.
//   agg = sum_s nodef[s,:] * os[s];  rst = leaky_relu(agg * is[d], 0.5)
//   emb[d,:] = rst
//   first!=0: acc_out[d,:] = init[d,:] + rst/||rst||   (init = A/B split at thresh)
//   first==0: acc_out[d,:] += rst/||rst||
// ---------------------------------------------------------------------------
__global__ __launch_bounds__(256)
void k_spmm(const float* __restrict__ nodef, const int* __restrict__ rp,
            const int* __restrict__ col, const float* __restrict__ osc,
            const float* __restrict__ isc,
            float* __restrict__ emb, float* __restrict__ acc_out, int n,
            int first, const float* __restrict__ initA,
            const float* __restrict__ initB, int thresh) {
    int w = (blockIdx.x * blockDim.x + threadIdx.x) >> 5;
    int lane = threadIdx.x & 31;
    if (w >= n) return;
    int b = __ldg(rp + w), e = __ldg(rp + w + 1);

    float4 a = make_float4(0.f, 0.f, 0.f, 0.f);
    for (int j = b; j < e; j += 8) {
        float4 v[8];
        float  o[8];
#pragma unroll
        for (int q = 0; q < 8; q++) {
            int jj = j + q;
            bool valid = jj < e;
            int s = valid ? __ldg(col + jj) : 0;
            o[q] = valid ? __ldg(osc + s) : 0.f;
            v[q] = valid
                ? __ldg(reinterpret_cast<const float4*>(nodef + (size_t)s * HID) + lane)
                : make_float4(0.f, 0.f, 0.f, 0.f);
        }
#pragma unroll
        for (int q = 0; q < 8; q++) {
            a.x = fmaf(v[q].x, o[q], a.x);
            a.y = fmaf(v[q].y, o[q], a.y);
            a.z = fmaf(v[q].z, o[q], a.z);
            a.w = fmaf(v[q].w, o[q], a.w);
        }
    }

    float sc = __ldg(isc + w);
    a.x *= sc; a.y *= sc; a.z *= sc; a.w *= sc;
    a.x = a.x >= 0.f ? a.x : 0.5f * a.x;
    a.y = a.y >= 0.f ? a.y : 0.5f * a.y;
    a.z = a.z >= 0.f ? a.z : 0.5f * a.z;
    a.w = a.w >= 0.f ? a.w : 0.5f * a.w;

    reinterpret_cast<float4*>(emb + (size_t)w * HID)[lane] = a;

    float sq = a.x * a.x + a.y * a.y + a.z * a.z + a.w * a.w;
#pragma unroll
    for (int o2 = 16; o2 > 0; o2 >>= 1)
        sq += __shfl_xor_sync(0xffffffffu, sq, o2);
    float inv = 1.0f / fmaxf(sqrtf(sq), 1e-12f);

    float4* op = reinterpret_cast<float4*>(acc_out + (size_t)w * HID) + lane;
    float4 o;
    if (first) {
        const float* ip = (w < thresh) ? (initA + (size_t)w * HID)
                                       : (initB + (size_t)(w - thresh) * HID);
        o = __ldg(reinterpret_cast<const float4*>(ip) + lane);
    } else {
        o = *op;
    }
    o.x += a.x * inv; o.y += a.y * inv; o.z += a.z * inv; o.w += a.w * inv;
    *op = o;
}

// ---------------------------------------------------------------------------
// Launch
// ---------------------------------------------------------------------------
extern "C" void kernel_launch(void* const* d_in, const int* in_sizes, int n_in,
                              void* d_out, int out_size) {
    (void)in_sizes; (void)n_in; (void)out_size;
    const float* user_emb = (const float*)d_in[0];
    const float* item_emb = (const float*)d_in[1];
    const float* ui_u_w   = (const float*)d_in[2];
    const float* ui_v_w   = (const float*)d_in[3];
    const float* uu_u_w   = (const float*)d_in[4];
    const int*   src_ui   = (const int*)d_in[5];
    const int*   dst_ui   = (const int*)d_in[6];
    const int*   src_uu   = (const int*)d_in[7];
    const int*   dst_uu   = (const int*)d_in[8];
    float* out = (float*)d_out;

    void* p;
    float *emb, *nodef, *os_ui, *is_ui, *os_uu, *is_uu;
    int *rp_ui, *cur_ui, *col_ui, *rp_uu, *cur_uu, *col_uu;
    int *do_ui, *di_ui, *do_uu, *di_uu, *bsum;
    cudaGetSymbolAddress(&p, g_emb);    emb    = (float*)p;
    cudaGetSymbolAddress(&p, g_nodef);  nodef  = (float*)p;
    cudaGetSymbolAddress(&p, g_os_ui);  os_ui  = (float*)p;
    cudaGetSymbolAddress(&p, g_is_ui);  is_ui  = (float*)p;
    cudaGetSymbolAddress(&p, g_os_uu);  os_uu  = (float*)p;
    cudaGetSymbolAddress(&p, g_is_uu);  is_uu  = (float*)p;
    cudaGetSymbolAddress(&p, g_rp_ui);  rp_ui  = (int*)p;
    cudaGetSymbolAddress(&p, g_cur_ui); cur_ui = (int*)p;
    cudaGetSymbolAddress(&p, g_col_ui); col_ui = (int*)p;
    cudaGetSymbolAddress(&p, g_rp_uu);  rp_uu  = (int*)p;
    cudaGetSymbolAddress(&p, g_cur_uu); cur_uu = (int*)p;
    cudaGetSymbolAddress(&p, g_col_uu); col_uu = (int*)p;
    cudaGetSymbolAddress(&p, g_do_ui);  do_ui  = (int*)p;
    cudaGetSymbolAddress(&p, g_di_ui);  di_ui  = (int*)p;
    cudaGetSymbolAddress(&p, g_do_uu);  do_uu  = (int*)p;
    cudaGetSymbolAddress(&p, g_di_uu);  di_uu  = (int*)p;
    cudaGetSymbolAddress(&p, g_bsum);   bsum   = (int*)p;

    cudaFuncSetAttribute(k_gemm, cudaFuncAttributeMaxDynamicSharedMemorySize, GEMM_SMEM);

    cudaStream_t st = 0;
    const int GU = (NUSER + 63) / 64;   // 1563
    const int GI = (NITEM + 63) / 64;   // 3125

    // ---- layer-0 GEMMs read inputs directly ----
    k_gemm<<<GU, 128, GEMM_SMEM, st>>>(user_emb, ui_u_w, nodef, NUSER);
    k_gemm<<<GI, 128, GEMM_SMEM, st>>>(item_emb, ui_v_w,
                                       nodef + (size_t)NUSER * HID, NITEM);

    // ---- graph preprocessing ----
    cudaMemsetAsync(do_ui, 0, NALL  * sizeof(int), st);
    cudaMemsetAsync(di_ui, 0, NALL  * sizeof(int), st);
    cudaMemsetAsync(do_uu, 0, NUSER * sizeof(int), st);
    cudaMemsetAsync(di_uu, 0, NUSER * sizeof(int), st);
    k_hist<<<(EUI + 255) / 256, 256, 0, st>>>(src_ui, dst_ui, EUI, do_ui, di_ui);
    k_hist<<<(EUU + 255) / 256, 256, 0, st>>>(src_uu, dst_uu, EUU, do_uu, di_uu);
    {
        int nb = (NALL + 1 + 1023) / 1024;
        k_scan_block<<<nb, 1024, 0, st>>>(di_ui, NALL, rp_ui, bsum);
        k_scan_sums<<<1, 512, 0, st>>>(bsum, nb);
        k_add<<<(NALL + 1 + 255) / 256, 256, 0, st>>>(rp_ui, cur_ui, bsum, NALL + 1);
    }
    {
        int nb = (NUSER + 1 + 1023) / 1024;
        k_scan_block<<<nb, 1024, 0, st>>>(di_uu, NUSER, rp_uu, bsum);
        k_scan_sums<<<1, 512, 0, st>>>(bsum, nb);
        k_add<<<(NUSER + 1 + 255) / 256, 256, 0, st>>>(rp_uu, cur_uu, bsum, NUSER + 1);
    }
    k_scales<<<(NALL  + 255) / 256, 256, 0, st>>>(do_ui, di_ui, os_ui, is_ui, NALL);
    k_scales<<<(NUSER + 255) / 256, 256, 0, st>>>(do_uu, di_uu, os_uu, is_uu, NUSER);
    k_scatter<<<(EUI + 255) / 256, 256, 0, st>>>(src_ui, dst_ui, EUI, cur_ui, col_ui);
    k_scatter<<<(EUU + 255) / 256, 256, 0, st>>>(src_uu, dst_uu, EUU, cur_uu, col_uu);
    k_sortrows<<<(NALL  + 255) / 256, 256, 0, st>>>(rp_ui, col_ui, NALL);
    k_sortrows<<<(NUSER + 255) / 256, 256, 0, st>>>(rp_uu, col_uu, NUSER);

    // ---- user-item propagation (out init fused into first spmm) ----
    k_spmm<<<(NALL + 7) / 8, 256, 0, st>>>(nodef, rp_ui, col_ui, os_ui, is_ui,
                                           emb, out, NALL,
                                           1, user_emb, item_emb, NUSER);
    for (int i = 1; i < LUI; i++) {
        k_gemm<<<GU, 128, GEMM_SMEM, st>>>(emb, ui_u_w + (size_t)i * HID * HID,
                                           nodef, NUSER);
        k_gemm<<<GI, 128, GEMM_SMEM, st>>>(emb + (size_t)NUSER * HID,
                                           ui_v_w + (size_t)i * HID * HID,
                                           nodef + (size_t)NUSER * HID, NITEM);
        k_spmm<<<(NALL + 7) / 8, 256, 0, st>>>(nodef, rp_ui, col_ui, os_ui, is_ui,
                                               emb, out, NALL,
                                               0, user_emb, item_emb, NUSER);
    }

    // ---- user-user (social) propagation ----
    k_gemm<<<GU, 128, GEMM_SMEM, st>>>(user_emb, uu_u_w, nodef, NUSER);
    k_spmm<<<(NUSER + 7) / 8, 256, 0, st>>>(nodef, rp_uu, col_uu, os_uu, is_uu,
                                            emb, out + (size_t)NALL * HID, NUSER,
                                            1, user_emb, user_emb, NUSER);
    for (int i = 1; i < LUU; i++) {
        k_gemm<<<GU, 128, GEMM_SMEM, st>>>(emb, uu_u_w + (size_t)i * HID * HID,
                                           nodef, NUSER);
        k_spmm<<<(NUSER + 7) / 8, 256, 0, st>>>(nodef, rp_uu, col_uu, os_uu, is_uu,
                                                emb, out + (size_t)NALL * HID, NUSER,
                                                0, user_emb, user_emb, NUSER);
    }
}

// round 16
// speedup vs baseline: 2.2268x; 1.0689x over previous
#include <cuda_runtime.h>
#include <cuda_bf16.h>
#include <cuda_fp16.h>
#include <cstdint>
#include <stdint.h>
#include <math.h>

// ---------------------------------------------------------------------------
// Problem constants
// ---------------------------------------------------------------------------
#define NUSER 100000
#define NITEM 200000
#define NALL  300000
#define HID   128
#define EUI   2000000
#define EUU   800000
#define LUI   3
#define LUU   2

#define APITCH 136   // bf16 elements per SMEM row (272B: conflict-free ldmatrix)
// smem: A hi/lo (64 rows) + W hi/lo (128 rows), bf16
#define GEMM_SMEM ((2 * 64 + 2 * 128) * APITCH * 2)   // 104448 B -> 2 CTAs/SM

// ---------------------------------------------------------------------------
// Scratch (device globals — no allocation allowed)
// ---------------------------------------------------------------------------
__device__ float  g_emb  [(size_t)NALL * HID];
__device__ __half g_nodef[(size_t)NALL * HID];   // fp16 intermediate (halves gather bytes)

__device__ int   g_rp_ui [NALL + 1];
__device__ int   g_cur_ui[NALL];
__device__ int   g_col_ui[EUI];
__device__ int   g_rp_uu [NUSER + 1];
__device__ int   g_cur_uu[NUSER];
__device__ int   g_col_uu[EUU];

__device__ int   g_do_ui[NALL];
__device__ int   g_di_ui[NALL];
__device__ int   g_do_uu[NUSER];
__device__ int   g_di_uu[NUSER];

__device__ float g_os_ui[NALL];
__device__ float g_is_ui[NALL];
__device__ float g_os_uu[NUSER];
__device__ float g_is_uu[NUSER];

__device__ int   g_bsum[512];

// ---------------------------------------------------------------------------
// Preprocessing kernels (unchanged)
// ---------------------------------------------------------------------------
__global__ void k_hist(const int* __restrict__ src, const int* __restrict__ dst,
                       int E, int* __restrict__ dsrc, int* __restrict__ ddst) {
    int i = blockIdx.x * blockDim.x + threadIdx.x;
    if (i < E) {
        atomicAdd(&dsrc[src[i]], 1);
        atomicAdd(&ddst[dst[i]], 1);
    }
}

__global__ void k_scan_block(const int* __restrict__ deg, int n,
                             int* __restrict__ out, int* __restrict__ bsum) {
    __shared__ int s[1024];
    int tid = threadIdx.x;
    int i = blockIdx.x * 1024 + tid;
    int v = (i < n) ? deg[i] : 0;
    s[tid] = v;
    __syncthreads();
    for (int off = 1; off < 1024; off <<= 1) {
        int t = (tid >= off) ? s[tid - off] : 0;
        __syncthreads();
        s[tid] += t;
        __syncthreads();
    }
    if (i <= n) out[i] = s[tid] - v;
    if (tid == 1023) bsum[blockIdx.x] = s[1023];
}

__global__ void k_scan_sums(int* __restrict__ bs, int nb) {
    __shared__ int s[512];
    int tid = threadIdx.x;
    int v = (tid < nb) ? bs[tid] : 0;
    s[tid] = v;
    __syncthreads();
    for (int off = 1; off < 512; off <<= 1) {
        int t = (tid >= off) ? s[tid - off] : 0;
        __syncthreads();
        s[tid] += t;
        __syncthreads();
    }
    if (tid < nb) bs[tid] = s[tid] - v;
}

__global__ void k_add(int* __restrict__ rp, int* __restrict__ cur,
                      const int* __restrict__ bs, int total) {
    int i = blockIdx.x * blockDim.x + threadIdx.x;
    if (i < total) {
        int v = rp[i] + bs[i >> 10];
        rp[i] = v;
        if (i < total - 1) cur[i] = v;
    }
}

__global__ void k_scales(const int* __restrict__ dout, const int* __restrict__ din,
                         float* __restrict__ os, float* __restrict__ is_, int n) {
    int i = blockIdx.x * blockDim.x + threadIdx.x;
    if (i < n) {
        os[i]  = rsqrtf(fmaxf((float)dout[i], 1.0f));
        is_[i] = rsqrtf(fmaxf((float)din[i],  1.0f));
    }
}

__global__ void k_scatter(const int* __restrict__ src, const int* __restrict__ dst,
                          int E, int* __restrict__ cur, int* __restrict__ col) {
    int i = blockIdx.x * blockDim.x + threadIdx.x;
    if (i < E) {
        int pos = atomicAdd(&cur[dst[i]], 1);
        col[pos] = src[i];
    }
}

__global__ void k_sortrows(const int* __restrict__ rp, int* __restrict__ col, int n) {
    int i = blockIdx.x * blockDim.x + threadIdx.x;
    if (i >= n) return;
    int b = rp[i], e = rp[i + 1];
    for (int j = b + 1; j < e; j++) {
        int key = col[j];
        int k = j - 1;
        while (k >= b && col[k] > key) { col[k + 1] = col[k]; k--; }
        col[k + 1] = key;
    }
}

// ---------------------------------------------------------------------------
// MMA helpers (unchanged)
// ---------------------------------------------------------------------------
__device__ __forceinline__ void cvt_split4(float4 v,
        __nv_bfloat162& h01, __nv_bfloat162& h23,
        __nv_bfloat162& l01, __nv_bfloat162& l23) {
    __nv_bfloat16 hx = __float2bfloat16_rn(v.x);
    __nv_bfloat16 hy = __float2bfloat16_rn(v.y);
    __nv_bfloat16 hz = __float2bfloat16_rn(v.z);
    __nv_bfloat16 hw = __float2bfloat16_rn(v.w);
    __nv_bfloat16 lx = __float2bfloat16_rn(v.x - __bfloat162float(hx));
    __nv_bfloat16 ly = __float2bfloat16_rn(v.y - __bfloat162float(hy));
    __nv_bfloat16 lz = __float2bfloat16_rn(v.z - __bfloat162float(hz));
    __nv_bfloat16 lw = __float2bfloat16_rn(v.w - __bfloat162float(hw));
    h01 = __nv_bfloat162(hx, hy); h23 = __nv_bfloat162(hz, hw);
    l01 = __nv_bfloat162(lx, ly); l23 = __nv_bfloat162(lz, lw);
}

__device__ __forceinline__ unsigned int smem_u32(const void* p) {
    return (unsigned int)__cvta_generic_to_shared(p);
}

__device__ __forceinline__ void ldsm_x4(unsigned int addr,
        unsigned int& r0, unsigned int& r1, unsigned int& r2, unsigned int& r3) {
    asm volatile("ldmatrix.sync.aligned.m8n8.x4.shared.b16 {%0,%1,%2,%3}, [%4];"
                 : "=r"(r0), "=r"(r1), "=r"(r2), "=r"(r3) : "r"(addr));
}
__device__ __forceinline__ void ldsm_x4t(unsigned int addr,
        unsigned int& r0, unsigned int& r1, unsigned int& r2, unsigned int& r3) {
    asm volatile("ldmatrix.sync.aligned.m8n8.x4.trans.shared.b16 {%0,%1,%2,%3}, [%4];"
                 : "=r"(r0), "=r"(r1), "=r"(r2), "=r"(r3) : "r"(addr));
}
__device__ __forceinline__ void mma16816(float* c,
        unsigned int a0, unsigned int a1, unsigned int a2, unsigned int a3,
        unsigned int b0, unsigned int b1) {
    asm volatile("mma.sync.aligned.m16n8k16.row.col.f32.bf16.bf16.f32 "
                 "{%0,%1,%2,%3}, {%4,%5,%6,%7}, {%8,%9}, {%0,%1,%2,%3};"
                 : "+f"(c[0]), "+f"(c[1]), "+f"(c[2]), "+f"(c[3])
                 : "r"(a0), "r"(a1), "r"(a2), "r"(a3), "r"(b0), "r"(b1));
}

// ---------------------------------------------------------------------------
// Tensor-core GEMM: C(fp16) = A(fp32) @ W(fp32), 64x128 tile, 2 CTA/SM.
// ---------------------------------------------------------------------------
__global__ __launch_bounds__(128, 2)
void k_gemm(const float* __restrict__ A, const float* __restrict__ W,
            __half* __restrict__ C, int M) {
    extern __shared__ __align__(16) unsigned char smem[];
    __nv_bfloat16* Ah = reinterpret_cast<__nv_bfloat16*>(smem);
    __nv_bfloat16* Al = Ah + 64 * APITCH;
    __nv_bfloat16* Wh = Al + 64 * APITCH;
    __nv_bfloat16* Wl = Wh + 128 * APITCH;

    const int tid = threadIdx.x;
    const int row0 = blockIdx.x * 64;

    // ---- stage A (64 rows) as bf16 hi/lo ----
#pragma unroll
    for (int i = 0; i < 16; i++) {
        int idx = tid + i * 128;
        int r  = idx >> 5;
        int c4 = idx & 31;
        float4 va = make_float4(0.f, 0.f, 0.f, 0.f);
        if (row0 + r < M)
            va = *reinterpret_cast<const float4*>(A + (size_t)(row0 + r) * 128 + c4 * 4);
        __nv_bfloat162 h01, h23, l01, l23;
        cvt_split4(va, h01, h23, l01, l23);
        __nv_bfloat162* pa = reinterpret_cast<__nv_bfloat162*>(Ah + r * APITCH + c4 * 4);
        pa[0] = h01; pa[1] = h23;
        __nv_bfloat162* pal = reinterpret_cast<__nv_bfloat162*>(Al + r * APITCH + c4 * 4);
        pal[0] = l01; pal[1] = l23;
    }
    // ---- stage W (128 k-rows) as bf16 hi/lo ----
#pragma unroll
    for (int i = 0; i < 32; i++) {
        int idx = tid + i * 128;
        int r  = idx >> 5;
        int c4 = idx & 31;
        float4 vw = *reinterpret_cast<const float4*>(W + (size_t)r * 128 + c4 * 4);
        __nv_bfloat162 h01, h23, l01, l23;
        cvt_split4(vw, h01, h23, l01, l23);
        __nv_bfloat162* pw = reinterpret_cast<__nv_bfloat162*>(Wh + r * APITCH + c4 * 4);
        pw[0] = h01; pw[1] = h23;
        __nv_bfloat162* pwl = reinterpret_cast<__nv_bfloat162*>(Wl + r * APITCH + c4 * 4);
        pwl[0] = l01; pwl[1] = l23;
    }
    __syncthreads();

    const int lane = tid & 31;
    const int w    = tid >> 5;
    const int m0   = w * 16;

    float acc[16][4];
#pragma unroll
    for (int i = 0; i < 16; i++)
#pragma unroll
        for (int j = 0; j < 4; j++) acc[i][j] = 0.0f;

    const int a_row  = m0 + (lane & 7) + (lane & 8);
    const int a_ksel = (lane >> 4) & 1;
    unsigned int aaddr_h = smem_u32(Ah + a_row * APITCH + a_ksel * 8);
    unsigned int aaddr_l = smem_u32(Al + a_row * APITCH + a_ksel * 8);
    const int b_krow = ((lane >> 4) & 1) * 8 + (lane & 7);
    const int b_nsel = (lane >> 3) & 1;
    unsigned int baddr_h = smem_u32(Wh + b_krow * APITCH + b_nsel * 8);
    unsigned int baddr_l = smem_u32(Wl + b_krow * APITCH + b_nsel * 8);

#pragma unroll
    for (int ks = 0; ks < 8; ks++) {
        const unsigned int koffA = ks * 32;
        const unsigned int koffB = ks * 16 * (APITCH * 2);
        unsigned int ah0, ah1, ah2, ah3, al0, al1, al2, al3;
        ldsm_x4(aaddr_h + koffA, ah0, ah1, ah2, ah3);
        ldsm_x4(aaddr_l + koffA, al0, al1, al2, al3);
#pragma unroll
        for (int ntp = 0; ntp < 8; ntp++) {
            unsigned int noff = ntp * 32;
            unsigned int bh0, bh1, bh2, bh3, bl0, bl1, bl2, bl3;
            ldsm_x4t(baddr_h + koffB + noff, bh0, bh1, bh2, bh3);
            ldsm_x4t(baddr_l + koffB + noff, bl0, bl1, bl2, bl3);
            mma16816(acc[ntp * 2],     ah0, ah1, ah2, ah3, bh0, bh2);
            mma16816(acc[ntp * 2],     al0, al1, al2, al3, bh0, bh2);
            mma16816(acc[ntp * 2],     ah0, ah1, ah2, ah3, bl0, bl2);
            mma16816(acc[ntp * 2 + 1], ah0, ah1, ah2, ah3, bh1, bh3);
            mma16816(acc[ntp * 2 + 1], al0, al1, al2, al3, bh1, bh3);
            mma16816(acc[ntp * 2 + 1], ah0, ah1, ah2, ah3, bl1, bl3);
        }
    }

    // ---- epilogue: write fp16 ----
    const int tr = lane >> 2;
    const int tc = (lane & 3) * 2;
    const int r_lo = row0 + m0 + tr;
    const int r_hi = r_lo + 8;
#pragma unroll
    for (int nt = 0; nt < 16; nt++) {
        int col = nt * 8 + tc;   // even -> 4B-aligned half2 store
        if (r_lo < M)
            *reinterpret_cast<__half2*>(C + (size_t)r_lo * 128 + col) =
                __floats2half2_rn(acc[nt][0], acc[nt][1]);
        if (r_hi < M)
            *reinterpret_cast<__half2*>(C + (size_t)r_hi * 128 + col) =
                __floats2half2_rn(acc[nt][2], acc[nt][3]);
    }
}

// ---------------------------------------------------------------------------
// CSR SpMM + fused epilogue. One warp per destination row, fp16 gather.
//   agg = sum_s nodef[s,:] * os[s];  rst = leaky_relu(agg * is[d], 0.5)
//   emb[d,:] = rst
//   first: acc_out[d,:] = init[d,:] + rst/||rst||; else acc_out += rst/||rst||
// ---------------------------------------------------------------------------
__global__ __launch_bounds__(256)
void k_spmm(const __half* __restrict__ nodef, const int* __restrict__ rp,
            const int* __restrict__ col, const float* __restrict__ osc,
            const float* __restrict__ isc,
            float* __restrict__ emb, float* __restrict__ acc_out, int n,
            int first, const float* __restrict__ initA,
            const float* __restrict__ initB, int thresh) {
    int w = (blockIdx.x * blockDim.x + threadIdx.x) >> 5;
    int lane = threadIdx.x & 31;
    if (w >= n) return;
    int b = __ldg(rp + w), e = __ldg(rp + w + 1);

    float4 a = make_float4(0.f, 0.f, 0.f, 0.f);
    for (int j = b; j < e; j += 8) {
        uint2  raw[8];
        float  o[8];
#pragma unroll
        for (int q = 0; q < 8; q++) {
            int jj = j + q;
            bool valid = jj < e;
            int s = valid ? __ldg(col + jj) : 0;
            o[q] = valid ? __ldg(osc + s) : 0.f;
            raw[q] = valid
                ? __ldg(reinterpret_cast<const uint2*>(nodef + (size_t)s * HID) + lane)
                : make_uint2(0u, 0u);
        }
#pragma unroll
        for (int q = 0; q < 8; q++) {
            __half2 h01 = *reinterpret_cast<__half2*>(&raw[q].x);
            __half2 h23 = *reinterpret_cast<__half2*>(&raw[q].y);
            float2 f01 = __half22float2(h01);
            float2 f23 = __half22float2(h23);
            a.x = fmaf(f01.x, o[q], a.x);
            a.y = fmaf(f01.y, o[q], a.y);
            a.z = fmaf(f23.x, o[q], a.z);
            a.w = fmaf(f23.y, o[q], a.w);
        }
    }

    float sc = __ldg(isc + w);
    a.x *= sc; a.y *= sc; a.z *= sc; a.w *= sc;
    a.x = a.x >= 0.f ? a.x : 0.5f * a.x;
    a.y = a.y >= 0.f ? a.y : 0.5f * a.y;
    a.z = a.z >= 0.f ? a.z : 0.5f * a.z;
    a.w = a.w >= 0.f ? a.w : 0.5f * a.w;

    reinterpret_cast<float4*>(emb + (size_t)w * HID)[lane] = a;

    float sq = a.x * a.x + a.y * a.y + a.z * a.z + a.w * a.w;
#pragma unroll
    for (int o2 = 16; o2 > 0; o2 >>= 1)
        sq += __shfl_xor_sync(0xffffffffu, sq, o2);
    float inv = 1.0f / fmaxf(sqrtf(sq), 1e-12f);

    float4* op = reinterpret_cast<float4*>(acc_out + (size_t)w * HID) + lane;
    float4 o;
    if (first) {
        const float* ip = (w < thresh) ? (initA + (size_t)w * HID)
                                       : (initB + (size_t)(w - thresh) * HID);
        o = __ldg(reinterpret_cast<const float4*>(ip) + lane);
    } else {
        o = *op;
    }
    o.x += a.x * inv; o.y += a.y * inv; o.z += a.z * inv; o.w += a.w * inv;
    *op = o;
}

// ---------------------------------------------------------------------------
// Launch
// ---------------------------------------------------------------------------
extern "C" void kernel_launch(void* const* d_in, const int* in_sizes, int n_in,
                              void* d_out, int out_size) {
    (void)in_sizes; (void)n_in; (void)out_size;
    const float* user_emb = (const float*)d_in[0];
    const float* item_emb = (const float*)d_in[1];
    const float* ui_u_w   = (const float*)d_in[2];
    const float* ui_v_w   = (const float*)d_in[3];
    const float* uu_u_w   = (const float*)d_in[4];
    const int*   src_ui   = (const int*)d_in[5];
    const int*   dst_ui   = (const int*)d_in[6];
    const int*   src_uu   = (const int*)d_in[7];
    const int*   dst_uu   = (const int*)d_in[8];
    float* out = (float*)d_out;

    void* p;
    float *emb, *os_ui, *is_ui, *os_uu, *is_uu;
    __half* nodef;
    int *rp_ui, *cur_ui, *col_ui, *rp_uu, *cur_uu, *col_uu;
    int *do_ui, *di_ui, *do_uu, *di_uu, *bsum;
    cudaGetSymbolAddress(&p, g_emb);    emb    = (float*)p;
    cudaGetSymbolAddress(&p, g_nodef);  nodef  = (__half*)p;
    cudaGetSymbolAddress(&p, g_os_ui);  os_ui  = (float*)p;
    cudaGetSymbolAddress(&p, g_is_ui);  is_ui  = (float*)p;
    cudaGetSymbolAddress(&p, g_os_uu);  os_uu  = (float*)p;
    cudaGetSymbolAddress(&p, g_is_uu);  is_uu  = (float*)p;
    cudaGetSymbolAddress(&p, g_rp_ui);  rp_ui  = (int*)p;
    cudaGetSymbolAddress(&p, g_cur_ui); cur_ui = (int*)p;
    cudaGetSymbolAddress(&p, g_col_ui); col_ui = (int*)p;
    cudaGetSymbolAddress(&p, g_rp_uu);  rp_uu  = (int*)p;
    cudaGetSymbolAddress(&p, g_cur_uu); cur_uu = (int*)p;
    cudaGetSymbolAddress(&p, g_col_uu); col_uu = (int*)p;
    cudaGetSymbolAddress(&p, g_do_ui);  do_ui  = (int*)p;
    cudaGetSymbolAddress(&p, g_di_ui);  di_ui  = (int*)p;
    cudaGetSymbolAddress(&p, g_do_uu);  do_uu  = (int*)p;
    cudaGetSymbolAddress(&p, g_di_uu);  di_uu  = (int*)p;
    cudaGetSymbolAddress(&p, g_bsum);   bsum   = (int*)p;

    cudaFuncSetAttribute(k_gemm, cudaFuncAttributeMaxDynamicSharedMemorySize, GEMM_SMEM);

    cudaStream_t st = 0;
    const int GU = (NUSER + 63) / 64;   // 1563
    const int GI = (NITEM + 63) / 64;   // 3125

    // ---- layer-0 GEMMs read inputs directly ----
    k_gemm<<<GU, 128, GEMM_SMEM, st>>>(user_emb, ui_u_w, nodef, NUSER);
    k_gemm<<<GI, 128, GEMM_SMEM, st>>>(item_emb, ui_v_w,
                                       nodef + (size_t)NUSER * HID, NITEM);

    // ---- graph preprocessing ----
    cudaMemsetAsync(do_ui, 0, NALL  * sizeof(int), st);
    cudaMemsetAsync(di_ui, 0, NALL  * sizeof(int), st);
    cudaMemsetAsync(do_uu, 0, NUSER * sizeof(int), st);
    cudaMemsetAsync(di_uu, 0, NUSER * sizeof(int), st);
    k_hist<<<(EUI + 255) / 256, 256, 0, st>>>(src_ui, dst_ui, EUI, do_ui, di_ui);
    k_hist<<<(EUU + 255) / 256, 256, 0, st>>>(src_uu, dst_uu, EUU, do_uu, di_uu);
    {
        int nb = (NALL + 1 + 1023) / 1024;
        k_scan_block<<<nb, 1024, 0, st>>>(di_ui, NALL, rp_ui, bsum);
        k_scan_sums<<<1, 512, 0, st>>>(bsum, nb);
        k_add<<<(NALL + 1 + 255) / 256, 256, 0, st>>>(rp_ui, cur_ui, bsum, NALL + 1);
    }
    {
        int nb = (NUSER + 1 + 1023) / 1024;
        k_scan_block<<<nb, 1024, 0, st>>>(di_uu, NUSER, rp_uu, bsum);
        k_scan_sums<<<1, 512, 0, st>>>(bsum, nb);
        k_add<<<(NUSER + 1 + 255) / 256, 256, 0, st>>>(rp_uu, cur_uu, bsum, NUSER + 1);
    }
    k_scales<<<(NALL  + 255) / 256, 256, 0, st>>>(do_ui, di_ui, os_ui, is_ui, NALL);
    k_scales<<<(NUSER + 255) / 256, 256, 0, st>>>(do_uu, di_uu, os_uu, is_uu, NUSER);
    k_scatter<<<(EUI + 255) / 256, 256, 0, st>>>(src_ui, dst_ui, EUI, cur_ui, col_ui);
    k_scatter<<<(EUU + 255) / 256, 256, 0, st>>>(src_uu, dst_uu, EUU, cur_uu, col_uu);
    k_sortrows<<<(NALL  + 255) / 256, 256, 0, st>>>(rp_ui, col_ui, NALL);
    k_sortrows<<<(NUSER + 255) / 256, 256, 0, st>>>(rp_uu, col_uu, NUSER);

    // ---- user-item propagation (out init fused into first spmm) ----
    k_spmm<<<(NALL + 7) / 8, 256, 0, st>>>(nodef, rp_ui, col_ui, os_ui, is_ui,
                                           emb, out, NALL,
                                           1, user_emb, item_emb, NUSER);
    for (int i = 1; i < LUI; i++) {
        k_gemm<<<GU, 128, GEMM_SMEM, st>>>(emb, ui_u_w + (size_t)i * HID * HID,
                                           nodef, NUSER);
        k_gemm<<<GI, 128, GEMM_SMEM, st>>>(emb + (size_t)NUSER * HID,
                                           ui_v_w + (size_t)i * HID * HID,
                                           nodef + (size_t)NUSER * HID, NITEM);
        k_spmm<<<(NALL + 7) / 8, 256, 0, st>>>(nodef, rp_ui, col_ui, os_ui, is_ui,
                                               emb, out, NALL,
                                               0, user_emb, item_emb, NUSER);
    }

    // ---- user-user (social) propagation ----
    k_gemm<<<GU, 128, GEMM_SMEM, st>>>(user_emb, uu_u_w, nodef, NUSER);
    k_spmm<<<(NUSER + 7) / 8, 256, 0, st>>>(nodef, rp_uu, col_uu, os_uu, is_uu,
                                            emb, out + (size_t)NALL * HID, NUSER,
                                            1, user_emb, user_emb, NUSER);
    for (int i = 1; i < LUU; i++) {
        k_gemm<<<GU, 128, GEMM_SMEM, st>>>(emb, uu_u_w + (size_t)i * HID * HID,
                                           nodef, NUSER);
        k_spmm<<<(NUSER + 7) / 8, 256, 0, st>>>(nodef, rp_uu, col_uu, os_uu, is_uu,
                                                emb, out + (size_t)NALL * HID, NUSER,
                                                0, user_emb, user_emb, NUSER);
    }
}

// round 17
// speedup vs baseline: 2.4275x; 1.0901x over previous
#include <cuda_runtime.h>
#include <cuda_bf16.h>
#include <cuda_fp16.h>
#include <cstdint>
#include <stdint.h>
#include <math.h>

#define NUSER 100000
#define NITEM 200000
#define NALL  300000
#define HID   128
#define EUI   2000000
#define EUU   800000
#define LUI   3
#define LUU   2

#define APITCH 136
#define GEMM_SMEM ((2 * 64 + 2 * 128) * APITCH * 2)   // 104448 B -> 2 CTAs/SM

// ---------------------------------------------------------------------------
// Scratch
// ---------------------------------------------------------------------------
__device__ __half g_nodef[(size_t)NALL * HID];
__device__ __half g_e0   [(size_t)NALL * HID];
__device__ __half g_e1   [(size_t)NALL * HID];
__device__ __half g_e2   [(size_t)NALL * HID];
__device__ float  g_inv0 [NALL];
__device__ float  g_inv1 [NALL];
__device__ float  g_inv2 [NALL];

__device__ int   g_rp_ui [NALL + 1];
__device__ int   g_cur_ui[NALL];
__device__ int   g_col_ui[EUI];
__device__ int   g_rp_uu [NUSER + 1];
__device__ int   g_cur_uu[NUSER];
__device__ int   g_col_uu[EUU];

__device__ int   g_do_ui[NALL];
__device__ int   g_di_ui[NALL];
__device__ int   g_do_uu[NUSER];
__device__ int   g_di_uu[NUSER];

__device__ float g_os_ui[NALL];
__device__ float g_is_ui[NALL];
__device__ float g_os_uu[NUSER];
__device__ float g_is_uu[NUSER];

__device__ int   g_bsum[512];

// ---------------------------------------------------------------------------
// Preprocessing kernels (unchanged)
// ---------------------------------------------------------------------------
__global__ void k_hist(const int* __restrict__ src, const int* __restrict__ dst,
                       int E, int* __restrict__ dsrc, int* __restrict__ ddst) {
    int i = blockIdx.x * blockDim.x + threadIdx.x;
    if (i < E) {
        atomicAdd(&dsrc[src[i]], 1);
        atomicAdd(&ddst[dst[i]], 1);
    }
}

__global__ void k_scan_block(const int* __restrict__ deg, int n,
                             int* __restrict__ out, int* __restrict__ bsum) {
    __shared__ int s[1024];
    int tid = threadIdx.x;
    int i = blockIdx.x * 1024 + tid;
    int v = (i < n) ? deg[i] : 0;
    s[tid] = v;
    __syncthreads();
    for (int off = 1; off < 1024; off <<= 1) {
        int t = (tid >= off) ? s[tid - off] : 0;
        __syncthreads();
        s[tid] += t;
        __syncthreads();
    }
    if (i <= n) out[i] = s[tid] - v;
    if (tid == 1023) bsum[blockIdx.x] = s[1023];
}

__global__ void k_scan_sums(int* __restrict__ bs, int nb) {
    __shared__ int s[512];
    int tid = threadIdx.x;
    int v = (tid < nb) ? bs[tid] : 0;
    s[tid] = v;
    __syncthreads();
    for (int off = 1; off < 512; off <<= 1) {
        int t = (tid >= off) ? s[tid - off] : 0;
        __syncthreads();
        s[tid] += t;
        __syncthreads();
    }
    if (tid < nb) bs[tid] = s[tid] - v;
}

__global__ void k_add(int* __restrict__ rp, int* __restrict__ cur,
                      const int* __restrict__ bs, int total) {
    int i = blockIdx.x * blockDim.x + threadIdx.x;
    if (i < total) {
        int v = rp[i] + bs[i >> 10];
        rp[i] = v;
        if (i < total - 1) cur[i] = v;
    }
}

__global__ void k_scales(const int* __restrict__ dout, const int* __restrict__ din,
                         float* __restrict__ os, float* __restrict__ is_, int n) {
    int i = blockIdx.x * blockDim.x + threadIdx.x;
    if (i < n) {
        os[i]  = rsqrtf(fmaxf((float)dout[i], 1.0f));
        is_[i] = rsqrtf(fmaxf((float)din[i],  1.0f));
    }
}

__global__ void k_scatter(const int* __restrict__ src, const int* __restrict__ dst,
                          int E, int* __restrict__ cur, int* __restrict__ col) {
    int i = blockIdx.x * blockDim.x + threadIdx.x;
    if (i < E) {
        int pos = atomicAdd(&cur[dst[i]], 1);
        col[pos] = src[i];
    }
}

__global__ void k_sortrows(const int* __restrict__ rp, int* __restrict__ col, int n) {
    int i = blockIdx.x * blockDim.x + threadIdx.x;
    if (i >= n) return;
    int b = rp[i], e = rp[i + 1];
    for (int j = b + 1; j < e; j++) {
        int key = col[j];
        int k = j - 1;
        while (k >= b && col[k] > key) { col[k + 1] = col[k]; k--; }
        col[k + 1] = key;
    }
}

// ---------------------------------------------------------------------------
// MMA helpers
// ---------------------------------------------------------------------------
__device__ __forceinline__ void split2(float x, __nv_bfloat16& h, __nv_bfloat16& l) {
    h = __float2bfloat16_rn(x);
    l = __float2bfloat16_rn(x - __bfloat162float(h));
}

__device__ __forceinline__ void cvt_split4(float4 v,
        __nv_bfloat162& h01, __nv_bfloat162& h23,
        __nv_bfloat162& l01, __nv_bfloat162& l23) {
    __nv_bfloat16 hx, hy, hz, hw, lx, ly, lz, lw;
    split2(v.x, hx, lx); split2(v.y, hy, ly);
    split2(v.z, hz, lz); split2(v.w, hw, lw);
    h01 = __nv_bfloat162(hx, hy); h23 = __nv_bfloat162(hz, hw);
    l01 = __nv_bfloat162(lx, ly); l23 = __nv_bfloat162(lz, lw);
}

__device__ __forceinline__ unsigned int smem_u32(const void* p) {
    return (unsigned int)__cvta_generic_to_shared(p);
}

__device__ __forceinline__ void ldsm_x4(unsigned int addr,
        unsigned int& r0, unsigned int& r1, unsigned int& r2, unsigned int& r3) {
    asm volatile("ldmatrix.sync.aligned.m8n8.x4.shared.b16 {%0,%1,%2,%3}, [%4];"
                 : "=r"(r0), "=r"(r1), "=r"(r2), "=r"(r3) : "r"(addr));
}
__device__ __forceinline__ void ldsm_x4t(unsigned int addr,
        unsigned int& r0, unsigned int& r1, unsigned int& r2, unsigned int& r3) {
    asm volatile("ldmatrix.sync.aligned.m8n8.x4.trans.shared.b16 {%0,%1,%2,%3}, [%4];"
                 : "=r"(r0), "=r"(r1), "=r"(r2), "=r"(r3) : "r"(addr));
}
__device__ __forceinline__ void mma16816(float* c,
        unsigned int a0, unsigned int a1, unsigned int a2, unsigned int a3,
        unsigned int b0, unsigned int b1) {
    asm volatile("mma.sync.aligned.m16n8k16.row.col.f32.bf16.bf16.f32 "
                 "{%0,%1,%2,%3}, {%4,%5,%6,%7}, {%8,%9}, {%0,%1,%2,%3};"
                 : "+f"(c[0]), "+f"(c[1]), "+f"(c[2]), "+f"(c[3])
                 : "r"(a0), "r"(a1), "r"(a2), "r"(a3), "r"(b0), "r"(b1));
}

// Shared GEMM body after A is staged: stage W, MMA, fp16 epilogue.
__device__ __forceinline__ void gemm_body(
        __nv_bfloat16* Ah, __nv_bfloat16* Al,
        __nv_bfloat16* Wh, __nv_bfloat16* Wl,
        const float* __restrict__ W, __half* __restrict__ C,
        int tid, int row0, int M) {
#pragma unroll
    for (int i = 0; i < 32; i++) {
        int idx = tid + i * 128;
        int r  = idx >> 5;
        int c4 = idx & 31;
        float4 vw = *reinterpret_cast<const float4*>(W + (size_t)r * 128 + c4 * 4);
        __nv_bfloat162 h01, h23, l01, l23;
        cvt_split4(vw, h01, h23, l01, l23);
        __nv_bfloat162* pw = reinterpret_cast<__nv_bfloat162*>(Wh + r * APITCH + c4 * 4);
        pw[0] = h01; pw[1] = h23;
        __nv_bfloat162* pwl = reinterpret_cast<__nv_bfloat162*>(Wl + r * APITCH + c4 * 4);
        pwl[0] = l01; pwl[1] = l23;
    }
    __syncthreads();

    const int lane = tid & 31;
    const int w    = tid >> 5;
    const int m0   = w * 16;

    float acc[16][4];
#pragma unroll
    for (int i = 0; i < 16; i++)
#pragma unroll
        for (int j = 0; j < 4; j++) acc[i][j] = 0.0f;

    const int a_row  = m0 + (lane & 7) + (lane & 8);
    const int a_ksel = (lane >> 4) & 1;
    unsigned int aaddr_h = smem_u32(Ah + a_row * APITCH + a_ksel * 8);
    unsigned int aaddr_l = smem_u32(Al + a_row * APITCH + a_ksel * 8);
    const int b_krow = ((lane >> 4) & 1) * 8 + (lane & 7);
    const int b_nsel = (lane >> 3) & 1;
    unsigned int baddr_h = smem_u32(Wh + b_krow * APITCH + b_nsel * 8);
    unsigned int baddr_l = smem_u32(Wl + b_krow * APITCH + b_nsel * 8);

#pragma unroll
    for (int ks = 0; ks < 8; ks++) {
        const unsigned int koffA = ks * 32;
        const unsigned int koffB = ks * 16 * (APITCH * 2);
        unsigned int ah0, ah1, ah2, ah3, al0, al1, al2, al3;
        ldsm_x4(aaddr_h + koffA, ah0, ah1, ah2, ah3);
        ldsm_x4(aaddr_l + koffA, al0, al1, al2, al3);
#pragma unroll
        for (int ntp = 0; ntp < 8; ntp++) {
            unsigned int noff = ntp * 32;
            unsigned int bh0, bh1, bh2, bh3, bl0, bl1, bl2, bl3;
            ldsm_x4t(baddr_h + koffB + noff, bh0, bh1, bh2, bh3);
            ldsm_x4t(baddr_l + koffB + noff, bl0, bl1, bl2, bl3);
            mma16816(acc[ntp * 2],     ah0, ah1, ah2, ah3, bh0, bh2);
            mma16816(acc[ntp * 2],     al0, al1, al2, al3, bh0, bh2);
            mma16816(acc[ntp * 2],     ah0, ah1, ah2, ah3, bl0, bl2);
            mma16816(acc[ntp * 2 + 1], ah0, ah1, ah2, ah3, bh1, bh3);
            mma16816(acc[ntp * 2 + 1], al0, al1, al2, al3, bh1, bh3);
            mma16816(acc[ntp * 2 + 1], ah0, ah1, ah2, ah3, bl1, bl3);
        }
    }

    const int tr = lane >> 2;
    const int tc = (lane & 3) * 2;
    const int r_lo = row0 + m0 + tr;
    const int r_hi = r_lo + 8;
#pragma unroll
    for (int nt = 0; nt < 16; nt++) {
        int col = nt * 8 + tc;
        if (r_lo < M)
            *reinterpret_cast<__half2*>(C + (size_t)r_lo * 128 + col) =
                __floats2half2_rn(acc[nt][0], acc[nt][1]);
        if (r_hi < M)
            *reinterpret_cast<__half2*>(C + (size_t)r_hi * 128 + col) =
                __floats2half2_rn(acc[nt][2], acc[nt][3]);
    }
}

// GEMM with fp32 A (layer-0 inputs)
__global__ __launch_bounds__(128, 2)
void k_gemm_f32(const float* __restrict__ A, const float* __restrict__ W,
                __half* __restrict__ C, int M) {
    extern __shared__ __align__(16) unsigned char smem[];
    __nv_bfloat16* Ah = reinterpret_cast<__nv_bfloat16*>(smem);
    __nv_bfloat16* Al = Ah + 64 * APITCH;
    __nv_bfloat16* Wh = Al + 64 * APITCH;
    __nv_bfloat16* Wl = Wh + 128 * APITCH;
    const int tid = threadIdx.x;
    const int row0 = blockIdx.x * 64;
#pragma unroll
    for (int i = 0; i < 16; i++) {
        int idx = tid + i * 128;
        int r  = idx >> 5;
        int c4 = idx & 31;
        float4 va = make_float4(0.f, 0.f, 0.f, 0.f);
        if (row0 + r < M)
            va = *reinterpret_cast<const float4*>(A + (size_t)(row0 + r) * 128 + c4 * 4);
        __nv_bfloat162 h01, h23, l01, l23;
        cvt_split4(va, h01, h23, l01, l23);
        __nv_bfloat162* pa = reinterpret_cast<__nv_bfloat162*>(Ah + r * APITCH + c4 * 4);
        pa[0] = h01; pa[1] = h23;
        __nv_bfloat162* pal = reinterpret_cast<__nv_bfloat162*>(Al + r * APITCH + c4 * 4);
        pal[0] = l01; pal[1] = l23;
    }
    gemm_body(Ah, Al, Wh, Wl, W, C, tid, row0, M);
}

// GEMM with fp16 A (layer state)
__global__ __launch_bounds__(128, 2)
void k_gemm_f16(const __half* __restrict__ A, const float* __restrict__ W,
                __half* __restrict__ C, int M) {
    extern __shared__ __align__(16) unsigned char smem[];
    __nv_bfloat16* Ah = reinterpret_cast<__nv_bfloat16*>(smem);
    __nv_bfloat16* Al = Ah + 64 * APITCH;
    __nv_bfloat16* Wh = Al + 64 * APITCH;
    __nv_bfloat16* Wl = Wh + 128 * APITCH;
    const int tid = threadIdx.x;
    const int row0 = blockIdx.x * 64;
    // 64 rows x 128 halves = 1024 uint4 (8 halves each); 128 thr x 8 iters
#pragma unroll
    for (int i = 0; i < 8; i++) {
        int idx = tid + i * 128;
        int r  = idx >> 4;          // 16 uint4 per row
        int c8 = idx & 15;          // 8-half group
        uint4 raw = make_uint4(0u, 0u, 0u, 0u);
        if (row0 + r < M)
            raw = *reinterpret_cast<const uint4*>(A + (size_t)(row0 + r) * 128 + c8 * 8);
        float2 f0 = __half22float2(*reinterpret_cast<__half2*>(&raw.x));
        float2 f1 = __half22float2(*reinterpret_cast<__half2*>(&raw.y));
        float2 f2 = __half22float2(*reinterpret_cast<__half2*>(&raw.z));
        float2 f3 = __half22float2(*reinterpret_cast<__half2*>(&raw.w));
        __nv_bfloat162 h01, h23, l01, l23, h45, h67, l45, l67;
        cvt_split4(make_float4(f0.x, f0.y, f1.x, f1.y), h01, h23, l01, l23);
        cvt_split4(make_float4(f2.x, f2.y, f3.x, f3.y), h45, h67, l45, l67);
        __nv_bfloat162* pa = reinterpret_cast<__nv_bfloat162*>(Ah + r * APITCH + c8 * 8);
        pa[0] = h01; pa[1] = h23; pa[2] = h45; pa[3] = h67;
        __nv_bfloat162* pal = reinterpret_cast<__nv_bfloat162*>(Al + r * APITCH + c8 * 8);
        pal[0] = l01; pal[1] = l23; pal[2] = l45; pal[3] = l67;
    }
    gemm_body(Ah, Al, Wh, Wl, W, C, tid, row0, M);
}

// ---------------------------------------------------------------------------
// CSR SpMM: one warp per dst row; fp16 gather; writes fp16 layer state + inv-norm.
// ---------------------------------------------------------------------------
__global__ __launch_bounds__(256)
void k_spmm(const __half* __restrict__ nodef, const int* __restrict__ rp,
            const int* __restrict__ col, const float* __restrict__ osc,
            const float* __restrict__ isc,
            __half* __restrict__ emb_out, float* __restrict__ invout, int n) {
    int w = (blockIdx.x * blockDim.x + threadIdx.x) >> 5;
    int lane = threadIdx.x & 31;
    if (w >= n) return;
    int b = __ldg(rp + w), e = __ldg(rp + w + 1);

    float4 a = make_float4(0.f, 0.f, 0.f, 0.f);
    for (int j = b; j < e; j += 8) {
        uint2 raw[8];
        float o[8];
#pragma unroll
        for (int q = 0; q < 8; q++) {
            int jj = j + q;
            bool valid = jj < e;
            int s = valid ? __ldg(col + jj) : 0;
            o[q] = valid ? __ldg(osc + s) : 0.f;
            raw[q] = valid
                ? __ldg(reinterpret_cast<const uint2*>(nodef + (size_t)s * HID) + lane)
                : make_uint2(0u, 0u);
        }
#pragma unroll
        for (int q = 0; q < 8; q++) {
            float2 f01 = __half22float2(*reinterpret_cast<__half2*>(&raw[q].x));
            float2 f23 = __half22float2(*reinterpret_cast<__half2*>(&raw[q].y));
            a.x = fmaf(f01.x, o[q], a.x);
            a.y = fmaf(f01.y, o[q], a.y);
            a.z = fmaf(f23.x, o[q], a.z);
            a.w = fmaf(f23.y, o[q], a.w);
        }
    }

    float sc = __ldg(isc + w);
    a.x *= sc; a.y *= sc; a.z *= sc; a.w *= sc;
    a.x = a.x >= 0.f ? a.x : 0.5f * a.x;
    a.y = a.y >= 0.f ? a.y : 0.5f * a.y;
    a.z = a.z >= 0.f ? a.z : 0.5f * a.z;
    a.w = a.w >= 0.f ? a.w : 0.5f * a.w;

    // store fp16 layer state
    __half2 p01 = __floats2half2_rn(a.x, a.y);
    __half2 p23 = __floats2half2_rn(a.z, a.w);
    uint2 pk;
    pk.x = *reinterpret_cast<unsigned int*>(&p01);
    pk.y = *reinterpret_cast<unsigned int*>(&p23);
    reinterpret_cast<uint2*>(emb_out + (size_t)w * HID)[lane] = pk;

    float sq = a.x * a.x + a.y * a.y + a.z * a.z + a.w * a.w;
#pragma unroll
    for (int o2 = 16; o2 > 0; o2 >>= 1)
        sq += __shfl_xor_sync(0xffffffffu, sq, o2);
    if (lane == 0)
        invout[w] = 1.0f / fmaxf(sqrtf(sq), 1e-12f);
}

// ---------------------------------------------------------------------------
// Final combine: out[r,:] = init[r,:] + sum_l e_l[r,:]*inv_l[r]
// float4 granularity; nterms = 2 or 3.
// ---------------------------------------------------------------------------
__global__ __launch_bounds__(256)
void k_final(float* __restrict__ out,
             const float* __restrict__ initA, const float* __restrict__ initB,
             int thresh,
             const __half* __restrict__ e0, const float* __restrict__ i0,
             const __half* __restrict__ e1, const float* __restrict__ i1,
             const __half* __restrict__ e2, const float* __restrict__ i2,
             int nterms, int n) {
    int idx = blockIdx.x * blockDim.x + threadIdx.x;   // over n*32 float4s
    if (idx >= n * 32) return;
    int row = idx >> 5;
    int c4  = idx & 31;
    const float* ip = (row < thresh) ? (initA + (size_t)row * HID)
                                     : (initB + (size_t)(row - thresh) * HID);
    float4 o = __ldg(reinterpret_cast<const float4*>(ip) + c4);

    uint2 r0 = __ldg(reinterpret_cast<const uint2*>(e0 + (size_t)row * HID) + c4);
    float v0 = __ldg(i0 + row);
    {
        float2 f01 = __half22float2(*reinterpret_cast<__half2*>(&r0.x));
        float2 f23 = __half22float2(*reinterpret_cast<__half2*>(&r0.y));
        o.x = fmaf(f01.x, v0, o.x); o.y = fmaf(f01.y, v0, o.y);
        o.z = fmaf(f23.x, v0, o.z); o.w = fmaf(f23.y, v0, o.w);
    }
    uint2 r1 = __ldg(reinterpret_cast<const uint2*>(e1 + (size_t)row * HID) + c4);
    float v1 = __ldg(i1 + row);
    {
        float2 f01 = __half22float2(*reinterpret_cast<__half2*>(&r1.x));
        float2 f23 = __half22float2(*reinterpret_cast<__half2*>(&r1.y));
        o.x = fmaf(f01.x, v1, o.x); o.y = fmaf(f01.y, v1, o.y);
        o.z = fmaf(f23.x, v1, o.z); o.w = fmaf(f23.y, v1, o.w);
    }
    if (nterms > 2) {
        uint2 r2 = __ldg(reinterpret_cast<const uint2*>(e2 + (size_t)row * HID) + c4);
        float v2 = __ldg(i2 + row);
        float2 f01 = __half22float2(*reinterpret_cast<__half2*>(&r2.x));
        float2 f23 = __half22float2(*reinterpret_cast<__half2*>(&r2.y));
        o.x = fmaf(f01.x, v2, o.x); o.y = fmaf(f01.y, v2, o.y);
        o.z = fmaf(f23.x, v2, o.z); o.w = fmaf(f23.y, v2, o.w);
    }
    reinterpret_cast<float4*>(out)[idx] = o;
}

// ---------------------------------------------------------------------------
// Launch
// ---------------------------------------------------------------------------
extern "C" void kernel_launch(void* const* d_in, const int* in_sizes, int n_in,
                              void* d_out, int out_size) {
    (void)in_sizes; (void)n_in; (void)out_size;
    const float* user_emb = (const float*)d_in[0];
    const float* item_emb = (const float*)d_in[1];
    const float* ui_u_w   = (const float*)d_in[2];
    const float* ui_v_w   = (const float*)d_in[3];
    const float* uu_u_w   = (const float*)d_in[4];
    const int*   src_ui   = (const int*)d_in[5];
    const int*   dst_ui   = (const int*)d_in[6];
    const int*   src_uu   = (const int*)d_in[7];
    const int*   dst_uu   = (const int*)d_in[8];
    float* out = (float*)d_out;

    void* p;
    __half *nodef, *e0, *e1, *e2;
    float *inv0, *inv1, *inv2;
    float *os_ui, *is_ui, *os_uu, *is_uu;
    int *rp_ui, *cur_ui, *col_ui, *rp_uu, *cur_uu, *col_uu;
    int *do_ui, *di_ui, *do_uu, *di_uu, *bsum;
    cudaGetSymbolAddress(&p, g_nodef);  nodef = (__half*)p;
    cudaGetSymbolAddress(&p, g_e0);     e0    = (__half*)p;
    cudaGetSymbolAddress(&p, g_e1);     e1    = (__half*)p;
    cudaGetSymbolAddress(&p, g_e2);     e2    = (__half*)p;
    cudaGetSymbolAddress(&p, g_inv0);   inv0  = (float*)p;
    cudaGetSymbolAddress(&p, g_inv1);   inv1  = (float*)p;
    cudaGetSymbolAddress(&p, g_inv2);   inv2  = (float*)p;
    cudaGetSymbolAddress(&p, g_os_ui);  os_ui  = (float*)p;
    cudaGetSymbolAddress(&p, g_is_ui);  is_ui  = (float*)p;
    cudaGetSymbolAddress(&p, g_os_uu);  os_uu  = (float*)p;
    cudaGetSymbolAddress(&p, g_is_uu);  is_uu  = (float*)p;
    cudaGetSymbolAddress(&p, g_rp_ui);  rp_ui  = (int*)p;
    cudaGetSymbolAddress(&p, g_cur_ui); cur_ui = (int*)p;
    cudaGetSymbolAddress(&p, g_col_ui); col_ui = (int*)p;
    cudaGetSymbolAddress(&p, g_rp_uu);  rp_uu  = (int*)p;
    cudaGetSymbolAddress(&p, g_cur_uu); cur_uu = (int*)p;
    cudaGetSymbolAddress(&p, g_col_uu); col_uu = (int*)p;
    cudaGetSymbolAddress(&p, g_do_ui);  do_ui  = (int*)p;
    cudaGetSymbolAddress(&p, g_di_ui);  di_ui  = (int*)p;
    cudaGetSymbolAddress(&p, g_do_uu);  do_uu  = (int*)p;
    cudaGetSymbolAddress(&p, g_di_uu);  di_uu  = (int*)p;
    cudaGetSymbolAddress(&p, g_bsum);   bsum   = (int*)p;

    cudaFuncSetAttribute(k_gemm_f32, cudaFuncAttributeMaxDynamicSharedMemorySize, GEMM_SMEM);
    cudaFuncSetAttribute(k_gemm_f16, cudaFuncAttributeMaxDynamicSharedMemorySize, GEMM_SMEM);

    cudaStream_t st = 0;
    const int GU = (NUSER + 63) / 64;
    const int GI = (NITEM + 63) / 64;
    const size_t OFF = (size_t)NUSER * HID;
    const size_t WS  = (size_t)HID * HID;

    // ---- layer-0 GEMMs ----
    k_gemm_f32<<<GU, 128, GEMM_SMEM, st>>>(user_emb, ui_u_w, nodef, NUSER);
    k_gemm_f32<<<GI, 128, GEMM_SMEM, st>>>(item_emb, ui_v_w, nodef + OFF, NITEM);

    // ---- graph preprocessing ----
    cudaMemsetAsync(do_ui, 0, NALL  * sizeof(int), st);
    cudaMemsetAsync(di_ui, 0, NALL  * sizeof(int), st);
    cudaMemsetAsync(do_uu, 0, NUSER * sizeof(int), st);
    cudaMemsetAsync(di_uu, 0, NUSER * sizeof(int), st);
    k_hist<<<(EUI + 255) / 256, 256, 0, st>>>(src_ui, dst_ui, EUI, do_ui, di_ui);
    k_hist<<<(EUU + 255) / 256, 256, 0, st>>>(src_uu, dst_uu, EUU, do_uu, di_uu);
    {
        int nb = (NALL + 1 + 1023) / 1024;
        k_scan_block<<<nb, 1024, 0, st>>>(di_ui, NALL, rp_ui, bsum);
        k_scan_sums<<<1, 512, 0, st>>>(bsum, nb);
        k_add<<<(NALL + 1 + 255) / 256, 256, 0, st>>>(rp_ui, cur_ui, bsum, NALL + 1);
    }
    {
        int nb = (NUSER + 1 + 1023) / 1024;
        k_scan_block<<<nb, 1024, 0, st>>>(di_uu, NUSER, rp_uu, bsum);
        k_scan_sums<<<1, 512, 0, st>>>(bsum, nb);
        k_add<<<(NUSER + 1 + 255) / 256, 256, 0, st>>>(rp_uu, cur_uu, bsum, NUSER + 1);
    }
    k_scales<<<(NALL  + 255) / 256, 256, 0, st>>>(do_ui, di_ui, os_ui, is_ui, NALL);
    k_scales<<<(NUSER + 255) / 256, 256, 0, st>>>(do_uu, di_uu, os_uu, is_uu, NUSER);
    k_scatter<<<(EUI + 255) / 256, 256, 0, st>>>(src_ui, dst_ui, EUI, cur_ui, col_ui);
    k_scatter<<<(EUU + 255) / 256, 256, 0, st>>>(src_uu, dst_uu, EUU, cur_uu, col_uu);
    k_sortrows<<<(NALL  + 255) / 256, 256, 0, st>>>(rp_ui, col_ui, NALL);
    k_sortrows<<<(NUSER + 255) / 256, 256, 0, st>>>(rp_uu, col_uu, NUSER);

    // ---- user-item propagation ----
    k_spmm<<<(NALL + 7) / 8, 256, 0, st>>>(nodef, rp_ui, col_ui, os_ui, is_ui,
                                           e0, inv0, NALL);
    k_gemm_f16<<<GU, 128, GEMM_SMEM, st>>>(e0, ui_u_w + WS, nodef, NUSER);
    k_gemm_f16<<<GI, 128, GEMM_SMEM, st>>>(e0 + OFF, ui_v_w + WS, nodef + OFF, NITEM);
    k_spmm<<<(NALL + 7) / 8, 256, 0, st>>>(nodef, rp_ui, col_ui, os_ui, is_ui,
                                           e1, inv1, NALL);
    k_gemm_f16<<<GU, 128, GEMM_SMEM, st>>>(e1, ui_u_w + 2 * WS, nodef, NUSER);
    k_gemm_f16<<<GI, 128, GEMM_SMEM, st>>>(e1 + OFF, ui_v_w + 2 * WS, nodef + OFF, NITEM);
    k_spmm<<<(NALL + 7) / 8, 256, 0, st>>>(nodef, rp_ui, col_ui, os_ui, is_ui,
                                           e2, inv2, NALL);
    k_final<<<(NALL * 32 + 255) / 256, 256, 0, st>>>(
        out, user_emb, item_emb, NUSER,
        e0, inv0, e1, inv1, e2, inv2, 3, NALL);

    // ---- user-user propagation ----
    k_gemm_f32<<<GU, 128, GEMM_SMEM, st>>>(user_emb, uu_u_w, nodef, NUSER);
    k_spmm<<<(NUSER + 7) / 8, 256, 0, st>>>(nodef, rp_uu, col_uu, os_uu, is_uu,
                                            e0, inv0, NUSER);
    k_gemm_f16<<<GU, 128, GEMM_SMEM, st>>>(e0, uu_u_w + WS, nodef, NUSER);
    k_spmm<<<(NUSER + 7) / 8, 256, 0, st>>>(nodef, rp_uu, col_uu, os_uu, is_uu,
                                            e1, inv1, NUSER);
    k_final<<<(NUSER * 32 + 255) / 256, 256, 0, st>>>(
        out + (size_t)NALL * HID, user_emb, user_emb, NUSER,
        e0, inv0, e1, inv1, e2, inv2, 2, NUSER);
}